// round 4
// baseline (speedup 1.0000x reference)
#include <cuda_runtime.h>
#include <cmath>

#define Bsz 2
#define SEQ 2048
#define DIM 2048
#define NH 16
#define KV_LORA 512
#define NOPE 128
#define ROPE_D 64
#define VD 128
#define QKD 192          // NOPE + ROPE
#define ROWS (Bsz*SEQ)   // 4096
#define QOUT (NH*QKD)    // 3072
#define KVA (KV_LORA+ROPE_D) // 576
#define KVB (NH*(NOPE+VD))   // 4096

// ---------------- scratch (static device memory; no runtime allocs) ----------------
__device__ float g_q[(size_t)ROWS*QOUT];
__device__ float g_kv[(size_t)ROWS*KVA];
__device__ float g_kvc[(size_t)ROWS*KV_LORA];
__device__ float g_kpe[(size_t)ROWS*ROPE_D];
__device__ float g_kvb[(size_t)ROWS*KVB];
__device__ float g_attn[(size_t)ROWS*(NH*VD)];

// ---------------- generic SGEMM: C[M,N] = A[M,K] @ B[N,K]^T ----------------
__global__ __launch_bounds__(256) void sgemm_nt(
    const float* __restrict__ A, const float* __restrict__ B, float* __restrict__ C,
    int M, int N, int K)
{
  __shared__ float As[16][128];
  __shared__ float Bs[16][128];
  const int tid = threadIdx.x;
  const int m0 = blockIdx.y * 128;
  const int n0 = blockIdx.x * 128;
  const int tx = tid & 15, ty = tid >> 4;

  float acc[8][8];
#pragma unroll
  for (int i = 0; i < 8; i++)
#pragma unroll
    for (int j = 0; j < 8; j++) acc[i][j] = 0.f;

  for (int k0 = 0; k0 < K; k0 += 16) {
#pragma unroll
    for (int it = 0; it < 2; it++) {
      int idx = tid + it * 256;
      int row = idx >> 2;
      int kq  = (idx & 3) * 4;
      float4 av = *(const float4*)(A + (size_t)(m0 + row) * K + k0 + kq);
      As[kq + 0][row] = av.x; As[kq + 1][row] = av.y;
      As[kq + 2][row] = av.z; As[kq + 3][row] = av.w;
      int bn = n0 + row;
      float4 bv = make_float4(0.f, 0.f, 0.f, 0.f);
      if (bn < N) bv = *(const float4*)(B + (size_t)bn * K + k0 + kq);
      Bs[kq + 0][row] = bv.x; Bs[kq + 1][row] = bv.y;
      Bs[kq + 2][row] = bv.z; Bs[kq + 3][row] = bv.w;
    }
    __syncthreads();
#pragma unroll
    for (int k = 0; k < 16; k++) {
      float4 a0 = *(const float4*)&As[k][ty * 8];
      float4 a1 = *(const float4*)&As[k][ty * 8 + 4];
      float4 b0 = *(const float4*)&Bs[k][tx * 8];
      float4 b1 = *(const float4*)&Bs[k][tx * 8 + 4];
      float a[8] = {a0.x, a0.y, a0.z, a0.w, a1.x, a1.y, a1.z, a1.w};
      float b[8] = {b0.x, b0.y, b0.z, b0.w, b1.x, b1.y, b1.z, b1.w};
#pragma unroll
      for (int i = 0; i < 8; i++)
#pragma unroll
        for (int j = 0; j < 8; j++) acc[i][j] = fmaf(a[i], b[j], acc[i][j]);
    }
    __syncthreads();
  }

#pragma unroll
  for (int i = 0; i < 8; i++) {
    int m = m0 + ty * 8 + i;
#pragma unroll
    for (int j = 0; j < 8; j++) {
      int n = n0 + tx * 8 + j;
      if (n < N) C[(size_t)m * N + n] = acc[i][j];
    }
  }
}

// ---------------- rmsnorm(kv_c) + rotary(k_pe) ----------------
// NOTE: reference applies RoPE ONLY to k_pe; the rotated q_pe in the reference
// is dead code (scores use the original, unrotated q). So q gets NO rotary.
__global__ __launch_bounds__(128) void kv_post_kernel(
    const float* __restrict__ w, const float* __restrict__ fc, const float* __restrict__ fs)
{
  int row = blockIdx.x;
  const float* kv = g_kv + (size_t)row * KVA;
  int t = threadIdx.x;
  float local[4];
  float ss = 0.f;
#pragma unroll
  for (int i = 0; i < 4; i++) { float v = kv[t + 128 * i]; local[i] = v; ss += v * v; }
#pragma unroll
  for (int o = 16; o >= 1; o >>= 1) ss += __shfl_xor_sync(0xffffffffu, ss, o);
  __shared__ float warp_ss[4];
  if ((t & 31) == 0) warp_ss[t >> 5] = ss;
  __syncthreads();
  float tot = warp_ss[0] + warp_ss[1] + warp_ss[2] + warp_ss[3];
  float norm = rsqrtf(tot * (1.f / 512.f) + 1e-6f);
#pragma unroll
  for (int i = 0; i < 4; i++)
    g_kvc[(size_t)row * KV_LORA + t + 128 * i] = local[i] * norm * w[t + 128 * i];

  if (t < 32) {
    int s = row & (SEQ - 1);
    float c  = fc[s * 32 + t];
    float sn = fs[s * 32 + t];
    float re = kv[KV_LORA + 2 * t], im = kv[KV_LORA + 2 * t + 1];
    g_kpe[(size_t)row * ROPE_D + 2 * t]     = re * c - im * sn;
    g_kpe[(size_t)row * ROPE_D + 2 * t + 1] = re * sn + im * c;
  }
}

// ---------------- causal flash attention ----------------
#define AQS 193
#define APS 65
__global__ __launch_bounds__(256) void attn_kernel(float scale)
{
  extern __shared__ float sm[];
  float* Qs = sm;                    // 64 * AQS
  float* Ks = Qs + 64 * AQS;         // 64 * AQS
  float* Vs = Ks + 64 * AQS;         // 64 * 128
  float* Ps = Vs + 64 * 128;         // 64 * APS

  const int qt = blockIdx.x;
  const int bh = blockIdx.y;
  const int b = bh >> 4, h = bh & 15;
  const int tid = threadIdx.x, tx = tid & 15, ty = tid >> 4;
  const int rowbase = b * SEQ;
  const int q0 = qt * 64;

  // load Q tile (pre-scaled); q is the RAW projection (no rotary!)
  for (int idx = tid; idx < 64 * QKD; idx += 256) {
    int r = idx / QKD, c = idx - r * QKD;
    Qs[r * AQS + c] = g_q[(size_t)(rowbase + q0 + r) * QOUT + h * QKD + c] * scale;
  }

  float m[4], l[4], acc[4][8];
#pragma unroll
  for (int ii = 0; ii < 4; ii++) {
    m[ii] = -1e30f; l[ii] = 0.f;
#pragma unroll
    for (int dd = 0; dd < 8; dd++) acc[ii][dd] = 0.f;
  }

  for (int kt = 0; kt <= qt; kt++) {
    const int k0 = kt * 64;
    // load K tile: [k_nope | k_pe]
    for (int idx = tid; idx < 64 * QKD; idx += 256) {
      int r = idx / QKD, c = idx - r * QKD;
      float v;
      if (c < NOPE) v = g_kvb[(size_t)(rowbase + k0 + r) * KVB + h * 256 + c];
      else          v = g_kpe[(size_t)(rowbase + k0 + r) * ROPE_D + (c - NOPE)];
      Ks[r * AQS + c] = v;
    }
    // load V tile
    for (int idx = tid; idx < 64 * VD; idx += 256) {
      int r = idx >> 7, c = idx & 127;
      Vs[r * 128 + c] = g_kvb[(size_t)(rowbase + k0 + r) * KVB + h * 256 + 128 + c];
    }
    __syncthreads();

    // scores: 4x4 per thread over QKD dims
    float s[4][4];
#pragma unroll
    for (int ii = 0; ii < 4; ii++)
#pragma unroll
      for (int cc = 0; cc < 4; cc++) s[ii][cc] = 0.f;
    for (int k = 0; k < QKD; k++) {
      float a[4], bb[4];
#pragma unroll
      for (int ii = 0; ii < 4; ii++) a[ii] = Qs[(ty + 16 * ii) * AQS + k];
#pragma unroll
      for (int cc = 0; cc < 4; cc++) bb[cc] = Ks[(tx + 16 * cc) * AQS + k];
#pragma unroll
      for (int ii = 0; ii < 4; ii++)
#pragma unroll
        for (int cc = 0; cc < 4; cc++) s[ii][cc] = fmaf(a[ii], bb[cc], s[ii][cc]);
    }

    if (kt == qt) {   // causal mask on the diagonal tile
#pragma unroll
      for (int ii = 0; ii < 4; ii++)
#pragma unroll
        for (int cc = 0; cc < 4; cc++)
          if (k0 + tx + 16 * cc > q0 + ty + 16 * ii) s[ii][cc] = -1e30f;
    }

    // online softmax per row (reduction over the 16-tx group; lanes
    // tx 0..15 of each half-warp hold the same row -> xor-shuffle width 16)
#pragma unroll
    for (int ii = 0; ii < 4; ii++) {
      float mx = fmaxf(fmaxf(s[ii][0], s[ii][1]), fmaxf(s[ii][2], s[ii][3]));
#pragma unroll
      for (int o = 8; o >= 1; o >>= 1) mx = fmaxf(mx, __shfl_xor_sync(0xffffffffu, mx, o));
      float mn = fmaxf(m[ii], mx);
      float corr = __expf(m[ii] - mn);
      m[ii] = mn;
      float rs = 0.f;
#pragma unroll
      for (int cc = 0; cc < 4; cc++) {
        float p = __expf(s[ii][cc] - mn);
        s[ii][cc] = p;
        rs += p;
      }
#pragma unroll
      for (int o = 8; o >= 1; o >>= 1) rs += __shfl_xor_sync(0xffffffffu, rs, o);
      l[ii] = l[ii] * corr + rs;
#pragma unroll
      for (int dd = 0; dd < 8; dd++) acc[ii][dd] *= corr;
#pragma unroll
      for (int cc = 0; cc < 4; cc++)
        Ps[(ty + 16 * ii) * APS + tx + 16 * cc] = s[ii][cc];
    }
    __syncthreads();

    // O += P @ V
    for (int j = 0; j < 64; j++) {
      float vv[8];
#pragma unroll
      for (int dd = 0; dd < 8; dd++) vv[dd] = Vs[j * 128 + tx + 16 * dd];
#pragma unroll
      for (int ii = 0; ii < 4; ii++) {
        float p = Ps[(ty + 16 * ii) * APS + j];
#pragma unroll
        for (int dd = 0; dd < 8; dd++) acc[ii][dd] = fmaf(p, vv[dd], acc[ii][dd]);
      }
    }
    __syncthreads();
  }

  // epilogue: normalize and store
#pragma unroll
  for (int ii = 0; ii < 4; ii++) {
    float inv = 1.f / l[ii];
    int r = rowbase + q0 + ty + 16 * ii;
#pragma unroll
    for (int dd = 0; dd < 8; dd++)
      g_attn[(size_t)r * (NH * VD) + h * VD + tx + 16 * dd] = acc[ii][dd] * inv;
  }
}

// ---------------- launcher ----------------
extern "C" void kernel_launch(void* const* d_in, const int* in_sizes, int n_in,
                              void* d_out, int out_size)
{
  // resolve inputs BY SIZE (robust to metadata ordering); the two freq
  // arrays share a size — first occurrence = cos, second = sin.
  const float *x = nullptr, *wq = nullptr, *wkv_a = nullptr, *kvnw = nullptr,
              *wkv_b = nullptr, *wo = nullptr, *fcos = nullptr, *fsin = nullptr;
  for (int i = 0; i < n_in; i++) {
    const float* p = (const float*)d_in[i];
    switch (in_sizes[i]) {
      case 8388608: x = p; break;          // 2*2048*2048
      case 6291456: wq = p; break;         // 3072*2048
      case 1179648: wkv_a = p; break;      // 576*2048
      case 512:     kvnw = p; break;       // 512
      case 2097152: wkv_b = p; break;      // 4096*512
      case 4194304: wo = p; break;         // 2048*2048
      case 65536:   if (!fcos) fcos = p; else fsin = p; break;  // 2048*32
      default: break;
    }
  }
  float* out = (float*)d_out;

  float *p_q, *p_kv, *p_kvc, *p_kvb, *p_attn;
  cudaGetSymbolAddress((void**)&p_q,    g_q);
  cudaGetSymbolAddress((void**)&p_kv,   g_kv);
  cudaGetSymbolAddress((void**)&p_kvc,  g_kvc);
  cudaGetSymbolAddress((void**)&p_kvb,  g_kvb);
  cudaGetSymbolAddress((void**)&p_attn, g_attn);

  // yarn mscale: m = 0.1*ln(40)+1; scale = m^2 / sqrt(192)
  double mm = 0.1 * log(40.0) + 1.0;
  float scale = (float)((1.0 / sqrt(192.0)) * mm * mm);

  // 1) q = x @ wq.T   (NO rotary on q — see note above)
  sgemm_nt<<<dim3((QOUT + 127) / 128, ROWS / 128), 256>>>(x, wq, p_q, ROWS, QOUT, DIM);
  // 2) kv = x @ wkv_a.T
  sgemm_nt<<<dim3((KVA + 127) / 128, ROWS / 128), 256>>>(x, wkv_a, p_kv, ROWS, KVA, DIM);
  // 3) rmsnorm + k_pe rotary
  kv_post_kernel<<<ROWS, 128>>>(kvnw, fcos, fsin);
  // 4) kvb = kv_c @ wkv_b.T
  sgemm_nt<<<dim3(KVB / 128, ROWS / 128), 256>>>(p_kvc, wkv_b, p_kvb, ROWS, KVB, KV_LORA);
  // 5) attention
  {
    size_t smem = (size_t)(64 * AQS * 2 + 64 * 128 + 64 * APS) * sizeof(float);
    cudaFuncSetAttribute(attn_kernel, cudaFuncAttributeMaxDynamicSharedMemorySize, (int)smem);
    attn_kernel<<<dim3(SEQ / 64, Bsz * NH), 256, smem>>>(scale);
  }
  // 6) out = attn @ wo.T
  sgemm_nt<<<dim3(DIM / 128, ROWS / 128), 256>>>(p_attn, wo, out, ROWS, DIM, NH * VD);
}

// round 5
// speedup vs baseline: 1.6407x; 1.6407x over previous
#include <cuda_runtime.h>
#include <cmath>
#include <cstdint>

#define Bsz 2
#define SEQ 2048
#define DIM 2048
#define NH 16
#define KV_LORA 512
#define NOPE 128
#define ROPE_D 64
#define VD 128
#define QKD 192
#define ROWS (Bsz*SEQ)
#define QOUT (NH*QKD)        // 3072
#define KVA (KV_LORA+ROPE_D) // 576
#define KVB (NH*(NOPE+VD))   // 4096

// ---------------- scratch ----------------
__device__ float g_q[(size_t)ROWS*QOUT];
__device__ float g_kv[(size_t)ROWS*KVA];
__device__ float g_kvc[(size_t)ROWS*KV_LORA];
__device__ float g_kpe[(size_t)ROWS*ROPE_D];
__device__ float g_kvb[(size_t)ROWS*KVB];
__device__ float g_attn[(size_t)ROWS*(NH*VD)];

// ---------------- tf32 helpers ----------------
__device__ __forceinline__ uint32_t f2tf(float x) {
  uint32_t y;
  asm("cvt.rna.tf32.f32 %0, %1;" : "=r"(y) : "f"(x));
  return y;
}
__device__ __forceinline__ void mma_tf32(float* c, const uint32_t* a, const uint32_t* b) {
  asm volatile(
      "mma.sync.aligned.m16n8k8.row.col.f32.tf32.tf32.f32 "
      "{%0,%1,%2,%3}, {%4,%5,%6,%7}, {%8,%9}, {%0,%1,%2,%3};\n"
      : "+f"(c[0]), "+f"(c[1]), "+f"(c[2]), "+f"(c[3])
      : "r"(a[0]), "r"(a[1]), "r"(a[2]), "r"(a[3]), "r"(b[0]), "r"(b[1]));
}

// ---------------- tf32 tensor GEMM: C[M,N] = A[M,K] @ B[N,K]^T ----------------
// BM=BN=128, BK=32. 256 threads = 8 warps (2x4), warp tile 64x32,
// per warp 4x4 grid of m16n8k8 mma. smem row stride 36 floats (conflict-free).
#define GST 36
__global__ __launch_bounds__(256) void tgemm_nt(
    const float* __restrict__ A, const float* __restrict__ B, float* __restrict__ C,
    int M, int N, int K)
{
  extern __shared__ uint32_t gsm[];
  uint32_t* As = gsm;                 // 128*36
  uint32_t* Bs = gsm + 128 * GST;     // 128*36

  const int tid = threadIdx.x;
  const int m0 = blockIdx.y * 128;
  const int n0 = blockIdx.x * 128;
  const int lane = tid & 31, warp = tid >> 5;
  const int g = lane >> 2, t = lane & 3;
  const int wm = warp >> 2, wn = warp & 3;   // 2 x 4 warp grid

  float acc[4][4][4];
#pragma unroll
  for (int i = 0; i < 4; i++)
#pragma unroll
    for (int j = 0; j < 4; j++)
#pragma unroll
      for (int r = 0; r < 4; r++) acc[i][j][r] = 0.f;

  const int lrow = tid >> 3;          // 0..31
  const int lc4  = (tid & 7) * 4;     // 0,4,..,28

  for (int k0 = 0; k0 < K; k0 += 32) {
    // load A tile 128x32 (always in-bounds)
#pragma unroll
    for (int it = 0; it < 4; it++) {
      int row = lrow + it * 32;
      float4 v = *(const float4*)(A + (size_t)(m0 + row) * K + k0 + lc4);
      uint4 u = make_uint4(f2tf(v.x), f2tf(v.y), f2tf(v.z), f2tf(v.w));
      *(uint4*)&As[row * GST + lc4] = u;
    }
    // load B tile 128x32 (guard rows >= N)
#pragma unroll
    for (int it = 0; it < 4; it++) {
      int row = lrow + it * 32;
      int bn = n0 + row;
      float4 v = make_float4(0.f, 0.f, 0.f, 0.f);
      if (bn < N) v = *(const float4*)(B + (size_t)bn * K + k0 + lc4);
      uint4 u = make_uint4(f2tf(v.x), f2tf(v.y), f2tf(v.z), f2tf(v.w));
      *(uint4*)&Bs[row * GST + lc4] = u;
    }
    __syncthreads();

#pragma unroll
    for (int ks = 0; ks < 4; ks++) {
      const int kk = ks * 8;
      uint32_t af[4][4];
#pragma unroll
      for (int i = 0; i < 4; i++) {
        int base = (wm * 64 + i * 16 + g) * GST + kk + t;
        af[i][0] = As[base];
        af[i][1] = As[base + 8 * GST];
        af[i][2] = As[base + 4];
        af[i][3] = As[base + 8 * GST + 4];
      }
      uint32_t bf[4][2];
#pragma unroll
      for (int j = 0; j < 4; j++) {
        int base = (wn * 32 + j * 8 + g) * GST + kk + t;
        bf[j][0] = Bs[base];
        bf[j][1] = Bs[base + 4];
      }
#pragma unroll
      for (int i = 0; i < 4; i++)
#pragma unroll
        for (int j = 0; j < 4; j++) mma_tf32(acc[i][j], af[i], bf[j]);
    }
    __syncthreads();
  }

  // epilogue
#pragma unroll
  for (int i = 0; i < 4; i++) {
    int row  = m0 + wm * 64 + i * 16 + g;
    int row2 = row + 8;
#pragma unroll
    for (int j = 0; j < 4; j++) {
      int col = n0 + wn * 32 + j * 8 + 2 * t;
      if (col < N) {
        *(float2*)&C[(size_t)row  * N + col] = make_float2(acc[i][j][0], acc[i][j][1]);
        *(float2*)&C[(size_t)row2 * N + col] = make_float2(acc[i][j][2], acc[i][j][3]);
      }
    }
  }
}

// ---------------- rmsnorm(kv_c) + rotary(k_pe) ----------------
// Reference applies RoPE only to k_pe (rotated q_pe is dead code there).
__global__ __launch_bounds__(128) void kv_post_kernel(
    const float* __restrict__ w, const float* __restrict__ fc, const float* __restrict__ fs)
{
  int row = blockIdx.x;
  const float* kv = g_kv + (size_t)row * KVA;
  int t = threadIdx.x;
  float local[4];
  float ss = 0.f;
#pragma unroll
  for (int i = 0; i < 4; i++) { float v = kv[t + 128 * i]; local[i] = v; ss += v * v; }
#pragma unroll
  for (int o = 16; o >= 1; o >>= 1) ss += __shfl_xor_sync(0xffffffffu, ss, o);
  __shared__ float warp_ss[4];
  if ((t & 31) == 0) warp_ss[t >> 5] = ss;
  __syncthreads();
  float tot = warp_ss[0] + warp_ss[1] + warp_ss[2] + warp_ss[3];
  float norm = rsqrtf(tot * (1.f / 512.f) + 1e-6f);
#pragma unroll
  for (int i = 0; i < 4; i++)
    g_kvc[(size_t)row * KV_LORA + t + 128 * i] = local[i] * norm * w[t + 128 * i];

  if (t < 32) {
    int s = row & (SEQ - 1);
    float c  = fc[s * 32 + t];
    float sn = fs[s * 32 + t];
    float re = kv[KV_LORA + 2 * t], im = kv[KV_LORA + 2 * t + 1];
    g_kpe[(size_t)row * ROPE_D + 2 * t]     = re * c - im * sn;
    g_kpe[(size_t)row * ROPE_D + 2 * t + 1] = re * sn + im * c;
  }
}

// ---------------- causal flash attention ----------------
// BM=BN=64, 256 threads. Q/K row stride 196 (16B aligned, 2-phase frag loads).
// V repacked: Vs[j*140 + tx*8 + (tx>>2)*4 + dd] = V[j][tx+16*dd]
// (16B stagger every 4 lanes -> each bank quad hit exactly 2x per load).
#define AQS 196
#define APS 65
#define VSTR 140
__global__ __launch_bounds__(256) void attn_kernel(float scale)
{
  extern __shared__ float sm[];
  float* Qs = sm;                    // 64 * 196
  float* Ks = Qs + 64 * AQS;         // 64 * 196
  float* Vs = Ks + 64 * AQS;         // 64 * 140
  float* Ps = Vs + 64 * VSTR;        // 64 * 65

  const int qt = blockIdx.x;
  const int bh = blockIdx.y;
  const int b = bh >> 4, h = bh & 15;
  const int tid = threadIdx.x, tx = tid & 15, ty = tid >> 4;
  const int rowbase = b * SEQ;
  const int q0 = qt * 64;
  const int vofs = tx * 8 + (tx >> 2) * 4;

  // load Q tile (pre-scaled); raw q projection (no rotary)
  for (int idx = tid; idx < 64 * QKD; idx += 256) {
    int r = idx / QKD, c = idx - r * QKD;
    Qs[r * AQS + c] = g_q[(size_t)(rowbase + q0 + r) * QOUT + h * QKD + c] * scale;
  }

  float m[4], l[4], acc[4][8];
#pragma unroll
  for (int ii = 0; ii < 4; ii++) {
    m[ii] = -1e30f; l[ii] = 0.f;
#pragma unroll
    for (int dd = 0; dd < 8; dd++) acc[ii][dd] = 0.f;
  }

  for (int kt = 0; kt <= qt; kt++) {
    const int k0 = kt * 64;
    // K tile: [k_nope | k_pe]
    for (int idx = tid; idx < 64 * QKD; idx += 256) {
      int r = idx / QKD, c = idx - r * QKD;
      float v;
      if (c < NOPE) v = g_kvb[(size_t)(rowbase + k0 + r) * KVB + h * 256 + c];
      else          v = g_kpe[(size_t)(rowbase + k0 + r) * ROPE_D + (c - NOPE)];
      Ks[r * AQS + c] = v;
    }
    // V tile, repacked
    for (int idx = tid; idx < 64 * VD; idx += 256) {
      int j = idx >> 7, c = idx & 127;
      int txx = c & 15, dd = c >> 4;
      Vs[j * VSTR + txx * 8 + (txx >> 2) * 4 + dd] =
          g_kvb[(size_t)(rowbase + k0 + j) * KVB + h * 256 + 128 + c];
    }
    __syncthreads();

    // scores: 4x4 per thread, float4 k-unroll with register fragments
    float s[4][4];
#pragma unroll
    for (int ii = 0; ii < 4; ii++)
#pragma unroll
      for (int cc = 0; cc < 4; cc++) s[ii][cc] = 0.f;
    for (int k = 0; k < QKD; k += 4) {
      float4 aF[4], bF[4];
#pragma unroll
      for (int ii = 0; ii < 4; ii++) aF[ii] = *(const float4*)&Qs[(ty + 16 * ii) * AQS + k];
#pragma unroll
      for (int cc = 0; cc < 4; cc++) bF[cc] = *(const float4*)&Ks[(tx + 16 * cc) * AQS + k];
#pragma unroll
      for (int ii = 0; ii < 4; ii++)
#pragma unroll
        for (int cc = 0; cc < 4; cc++) {
          s[ii][cc] = fmaf(aF[ii].x, bF[cc].x, s[ii][cc]);
          s[ii][cc] = fmaf(aF[ii].y, bF[cc].y, s[ii][cc]);
          s[ii][cc] = fmaf(aF[ii].z, bF[cc].z, s[ii][cc]);
          s[ii][cc] = fmaf(aF[ii].w, bF[cc].w, s[ii][cc]);
        }
    }

    if (kt == qt) {
#pragma unroll
      for (int ii = 0; ii < 4; ii++)
#pragma unroll
        for (int cc = 0; cc < 4; cc++)
          if (k0 + tx + 16 * cc > q0 + ty + 16 * ii) s[ii][cc] = -1e30f;
    }

    // online softmax (width-16 xor reduction over tx lanes)
#pragma unroll
    for (int ii = 0; ii < 4; ii++) {
      float mx = fmaxf(fmaxf(s[ii][0], s[ii][1]), fmaxf(s[ii][2], s[ii][3]));
#pragma unroll
      for (int o = 8; o >= 1; o >>= 1) mx = fmaxf(mx, __shfl_xor_sync(0xffffffffu, mx, o));
      float mn = fmaxf(m[ii], mx);
      float corr = __expf(m[ii] - mn);
      m[ii] = mn;
      float rs = 0.f;
#pragma unroll
      for (int cc = 0; cc < 4; cc++) {
        float p = __expf(s[ii][cc] - mn);
        s[ii][cc] = p;
        rs += p;
      }
#pragma unroll
      for (int o = 8; o >= 1; o >>= 1) rs += __shfl_xor_sync(0xffffffffu, rs, o);
      l[ii] = l[ii] * corr + rs;
#pragma unroll
      for (int dd = 0; dd < 8; dd++) acc[ii][dd] *= corr;
#pragma unroll
      for (int cc = 0; cc < 4; cc++)
        Ps[(ty + 16 * ii) * APS + tx + 16 * cc] = s[ii][cc];
    }
    __syncthreads();

    // O += P @ V  (packed V: 2x LDS.128 per j)
    for (int j = 0; j < 64; j++) {
      float4 v0 = *(const float4*)&Vs[j * VSTR + vofs];
      float4 v1 = *(const float4*)&Vs[j * VSTR + vofs + 4];
      float vv[8] = {v0.x, v0.y, v0.z, v0.w, v1.x, v1.y, v1.z, v1.w};
#pragma unroll
      for (int ii = 0; ii < 4; ii++) {
        float p = Ps[(ty + 16 * ii) * APS + j];
#pragma unroll
        for (int dd = 0; dd < 8; dd++) acc[ii][dd] = fmaf(p, vv[dd], acc[ii][dd]);
      }
    }
    __syncthreads();
  }

#pragma unroll
  for (int ii = 0; ii < 4; ii++) {
    float inv = 1.f / l[ii];
    int r = rowbase + q0 + ty + 16 * ii;
#pragma unroll
    for (int dd = 0; dd < 8; dd++)
      g_attn[(size_t)r * (NH * VD) + h * VD + tx + 16 * dd] = acc[ii][dd] * inv;
  }
}

// ---------------- launcher ----------------
extern "C" void kernel_launch(void* const* d_in, const int* in_sizes, int n_in,
                              void* d_out, int out_size)
{
  const float *x = nullptr, *wq = nullptr, *wkv_a = nullptr, *kvnw = nullptr,
              *wkv_b = nullptr, *wo = nullptr, *fcos = nullptr, *fsin = nullptr;
  for (int i = 0; i < n_in; i++) {
    const float* p = (const float*)d_in[i];
    switch (in_sizes[i]) {
      case 8388608: x = p; break;
      case 6291456: wq = p; break;
      case 1179648: wkv_a = p; break;
      case 512:     kvnw = p; break;
      case 2097152: wkv_b = p; break;
      case 4194304: wo = p; break;
      case 65536:   if (!fcos) fcos = p; else fsin = p; break;
      default: break;
    }
  }
  float* out = (float*)d_out;

  float *p_q, *p_kv, *p_kvc, *p_kvb, *p_attn;
  cudaGetSymbolAddress((void**)&p_q,    g_q);
  cudaGetSymbolAddress((void**)&p_kv,   g_kv);
  cudaGetSymbolAddress((void**)&p_kvc,  g_kvc);
  cudaGetSymbolAddress((void**)&p_kvb,  g_kvb);
  cudaGetSymbolAddress((void**)&p_attn, g_attn);

  double mm = 0.1 * log(40.0) + 1.0;
  float scale = (float)((1.0 / sqrt(192.0)) * mm * mm);

  const size_t gsmem = (size_t)(2 * 128 * GST) * sizeof(uint32_t);   // 36864 B
  cudaFuncSetAttribute(tgemm_nt, cudaFuncAttributeMaxDynamicSharedMemorySize, (int)gsmem);

  // 1) q = x @ wq.T
  tgemm_nt<<<dim3(QOUT / 128, ROWS / 128), 256, gsmem>>>(x, wq, p_q, ROWS, QOUT, DIM);
  // 2) kv = x @ wkv_a.T   (N=576 -> 5 column blocks, guarded)
  tgemm_nt<<<dim3((KVA + 127) / 128, ROWS / 128), 256, gsmem>>>(x, wkv_a, p_kv, ROWS, KVA, DIM);
  // 3) rmsnorm + k_pe rotary
  kv_post_kernel<<<ROWS, 128>>>(kvnw, fcos, fsin);
  // 4) kvb = kv_c @ wkv_b.T
  tgemm_nt<<<dim3(KVB / 128, ROWS / 128), 256, gsmem>>>(p_kvc, wkv_b, p_kvb, ROWS, KVB, KV_LORA);
  // 5) attention
  {
    size_t smem = (size_t)(64 * AQS * 2 + 64 * VSTR + 64 * APS) * sizeof(float);
    cudaFuncSetAttribute(attn_kernel, cudaFuncAttributeMaxDynamicSharedMemorySize, (int)smem);
    attn_kernel<<<dim3(SEQ / 64, Bsz * NH), 256, smem>>>(scale);
  }
  // 6) out = attn @ wo.T
  tgemm_nt<<<dim3(DIM / 128, ROWS / 128), 256, gsmem>>>(p_attn, wo, out, ROWS, DIM, NH * VD);
}

// round 6
// speedup vs baseline: 1.7867x; 1.0890x over previous
#include <cuda_runtime.h>
#include <cmath>
#include <cstdint>

#define Bsz 2
#define SEQ 2048
#define DIM 2048
#define NH 16
#define KV_LORA 512
#define NOPE 128
#define ROPE_D 64
#define VD 128
#define QKD 192
#define ROWS (Bsz*SEQ)
#define QOUT (NH*QKD)        // 3072
#define KVA (KV_LORA+ROPE_D) // 576
#define KVB (NH*(NOPE+VD))   // 4096

// ---------------- scratch ----------------
__device__ float g_q[(size_t)ROWS*QOUT];
__device__ float g_kv[(size_t)ROWS*KVA];
__device__ float g_kvc[(size_t)ROWS*KV_LORA];
__device__ float g_kpe[(size_t)ROWS*ROPE_D];
__device__ float g_kvb[(size_t)ROWS*KVB];
__device__ float g_attn[(size_t)ROWS*(NH*VD)];

// ---------------- tf32 helpers ----------------
__device__ __forceinline__ uint32_t f2tf(float x) {
  uint32_t y;
  asm("cvt.rna.tf32.f32 %0, %1;" : "=r"(y) : "f"(x));
  return y;
}
__device__ __forceinline__ void tfsplit(float x, uint32_t& hi, uint32_t& lo) {
  hi = f2tf(x);
  lo = f2tf(x - __uint_as_float(hi));
}
__device__ __forceinline__ void mma_tf32(float* c, const uint32_t* a, const uint32_t* b) {
  asm volatile(
      "mma.sync.aligned.m16n8k8.row.col.f32.tf32.tf32.f32 "
      "{%0,%1,%2,%3}, {%4,%5,%6,%7}, {%8,%9}, {%0,%1,%2,%3};\n"
      : "+f"(c[0]), "+f"(c[1]), "+f"(c[2]), "+f"(c[3])
      : "r"(a[0]), "r"(a[1]), "r"(a[2]), "r"(a[3]), "r"(b[0]), "r"(b[1]));
}

// ---------------- tf32 tensor GEMM: C[M,N] = A[M,K] @ B[N,K]^T ----------------
#define GST 36
__global__ __launch_bounds__(256) void tgemm_nt(
    const float* __restrict__ A, const float* __restrict__ B, float* __restrict__ C,
    int M, int N, int K)
{
  extern __shared__ uint32_t gsm[];
  uint32_t* As = gsm;
  uint32_t* Bs = gsm + 128 * GST;

  const int tid = threadIdx.x;
  const int m0 = blockIdx.y * 128;
  const int n0 = blockIdx.x * 128;
  const int lane = tid & 31, warp = tid >> 5;
  const int g = lane >> 2, t = lane & 3;
  const int wm = warp >> 2, wn = warp & 3;

  float acc[4][4][4];
#pragma unroll
  for (int i = 0; i < 4; i++)
#pragma unroll
    for (int j = 0; j < 4; j++)
#pragma unroll
      for (int r = 0; r < 4; r++) acc[i][j][r] = 0.f;

  const int lrow = tid >> 3;
  const int lc4  = (tid & 7) * 4;

  for (int k0 = 0; k0 < K; k0 += 32) {
#pragma unroll
    for (int it = 0; it < 4; it++) {
      int row = lrow + it * 32;
      float4 v = *(const float4*)(A + (size_t)(m0 + row) * K + k0 + lc4);
      uint4 u = make_uint4(f2tf(v.x), f2tf(v.y), f2tf(v.z), f2tf(v.w));
      *(uint4*)&As[row * GST + lc4] = u;
    }
#pragma unroll
    for (int it = 0; it < 4; it++) {
      int row = lrow + it * 32;
      int bn = n0 + row;
      float4 v = make_float4(0.f, 0.f, 0.f, 0.f);
      if (bn < N) v = *(const float4*)(B + (size_t)bn * K + k0 + lc4);
      uint4 u = make_uint4(f2tf(v.x), f2tf(v.y), f2tf(v.z), f2tf(v.w));
      *(uint4*)&Bs[row * GST + lc4] = u;
    }
    __syncthreads();

#pragma unroll
    for (int ks = 0; ks < 4; ks++) {
      const int kk = ks * 8;
      uint32_t af[4][4];
#pragma unroll
      for (int i = 0; i < 4; i++) {
        int base = (wm * 64 + i * 16 + g) * GST + kk + t;
        af[i][0] = As[base];
        af[i][1] = As[base + 8 * GST];
        af[i][2] = As[base + 4];
        af[i][3] = As[base + 8 * GST + 4];
      }
      uint32_t bf[4][2];
#pragma unroll
      for (int j = 0; j < 4; j++) {
        int base = (wn * 32 + j * 8 + g) * GST + kk + t;
        bf[j][0] = Bs[base];
        bf[j][1] = Bs[base + 4];
      }
#pragma unroll
      for (int i = 0; i < 4; i++)
#pragma unroll
        for (int j = 0; j < 4; j++) mma_tf32(acc[i][j], af[i], bf[j]);
    }
    __syncthreads();
  }

#pragma unroll
  for (int i = 0; i < 4; i++) {
    int row  = m0 + wm * 64 + i * 16 + g;
    int row2 = row + 8;
#pragma unroll
    for (int j = 0; j < 4; j++) {
      int col = n0 + wn * 32 + j * 8 + 2 * t;
      if (col < N) {
        *(float2*)&C[(size_t)row  * N + col] = make_float2(acc[i][j][0], acc[i][j][1]);
        *(float2*)&C[(size_t)row2 * N + col] = make_float2(acc[i][j][2], acc[i][j][3]);
      }
    }
  }
}

// ---------------- rmsnorm(kv_c) + rotary(k_pe) ----------------
__global__ __launch_bounds__(128) void kv_post_kernel(
    const float* __restrict__ w, const float* __restrict__ fc, const float* __restrict__ fs)
{
  int row = blockIdx.x;
  const float* kv = g_kv + (size_t)row * KVA;
  int t = threadIdx.x;
  float local[4];
  float ss = 0.f;
#pragma unroll
  for (int i = 0; i < 4; i++) { float v = kv[t + 128 * i]; local[i] = v; ss += v * v; }
#pragma unroll
  for (int o = 16; o >= 1; o >>= 1) ss += __shfl_xor_sync(0xffffffffu, ss, o);
  __shared__ float warp_ss[4];
  if ((t & 31) == 0) warp_ss[t >> 5] = ss;
  __syncthreads();
  float tot = warp_ss[0] + warp_ss[1] + warp_ss[2] + warp_ss[3];
  float norm = rsqrtf(tot * (1.f / 512.f) + 1e-6f);
#pragma unroll
  for (int i = 0; i < 4; i++)
    g_kvc[(size_t)row * KV_LORA + t + 128 * i] = local[i] * norm * w[t + 128 * i];

  if (t < 32) {
    int s = row & (SEQ - 1);
    float c  = fc[s * 32 + t];
    float sn = fs[s * 32 + t];
    float re = kv[KV_LORA + 2 * t], im = kv[KV_LORA + 2 * t + 1];
    g_kpe[(size_t)row * ROPE_D + 2 * t]     = re * c - im * sn;
    g_kpe[(size_t)row * ROPE_D + 2 * t + 1] = re * sn + im * c;
  }
}

// ---------------- tensor-core causal flash attention (3xTF32) ----------------
// BM=BN=64, 256 threads = 8 warps.
// Scores: warp (wm=warp&3, wn=warp>>2): rows wm*16, cols wn*32 (4 n-blocks).
// PV:     same wm rows, cols wn*64 (8 n-blocks), K-dim = 64 P-columns.
#define QST 196   // Qs stride (fp32); 196 % 32 == 4 -> frag banks 4g+t distinct
#define KST 196   // K hi/lo strides
#define VTS 68    // transposed V stride
#define PST 68    // P stride
__global__ __launch_bounds__(256) void attn_kernel(float scale)
{
  extern __shared__ float sm[];
  float* Qs    = sm;                  // 64*196
  float* Kh    = Qs + 64 * QST;       // 64*196
  float* Kl    = Kh + 64 * KST;       // 64*196
  float* Vt    = Kl + 64 * KST;       // 128*68 (V transposed: Vt[c][j])
  float* Ps    = Vt + 128 * VTS;      // 64*68
  float* pmax  = Ps + 64 * PST;       // 64*2
  float* psum  = pmax + 128;          // 64*2
  float* row_m = psum + 128;          // 64
  float* row_l = row_m + 64;          // 64
  float* row_c = row_l + 64;          // 64

  const int qt = blockIdx.x, bh = blockIdx.y;
  const int b = bh >> 4, h = bh & 15;
  const int tid = threadIdx.x;
  const int lane = tid & 31, warp = tid >> 5;
  const int g = lane >> 2, t = lane & 3;
  const int wm = warp & 3, wn = warp >> 2;
  const int rowbase = b * SEQ, q0 = qt * 64;
  const int r0 = wm * 16 + g, r1 = r0 + 8;

  if (tid < 64) { row_m[tid] = -1e30f; row_l[tid] = 0.f; }

  // Q tile (pre-scaled, fp32; raw projection — reference's q-rotary is dead code)
  for (int idx = tid; idx < 64 * QKD; idx += 256) {
    int r = idx / QKD, c = idx - r * QKD;
    Qs[r * QST + c] = g_q[(size_t)(rowbase + q0 + r) * QOUT + h * QKD + c] * scale;
  }

  float oacc[8][4];
#pragma unroll
  for (int j = 0; j < 8; j++)
#pragma unroll
    for (int r = 0; r < 4; r++) oacc[j][r] = 0.f;

  for (int kt = 0; kt <= qt; kt++) {
    const int k0 = kt * 64;
    // K tile -> hi/lo tf32 smem
    for (int idx = tid; idx < 64 * QKD; idx += 256) {
      int r = idx / QKD, c = idx - r * QKD;
      float v = (c < NOPE)
          ? g_kvb[(size_t)(rowbase + k0 + r) * KVB + h * 256 + c]
          : g_kpe[(size_t)(rowbase + k0 + r) * ROPE_D + (c - NOPE)];
      uint32_t hb = f2tf(v);
      Kh[r * KST + c] = __uint_as_float(hb);
      Kl[r * KST + c] = __uint_as_float(f2tf(v - __uint_as_float(hb)));
    }
    // V tile, transposed (Vt[c][j])
    for (int idx = tid; idx < 64 * VD; idx += 256) {
      int j = idx >> 7, c = idx & 127;
      Vt[c * VTS + j] = g_kvb[(size_t)(rowbase + k0 + j) * KVB + h * 256 + 128 + c];
    }
    __syncthreads();

    // ---- scores: S = Q @ K^T (3xTF32) ----
    float sacc[4][4];
#pragma unroll
    for (int j = 0; j < 4; j++)
#pragma unroll
      for (int r = 0; r < 4; r++) sacc[j][r] = 0.f;

    for (int kk = 0; kk < QKD / 8; kk++) {
      const int ko = kk * 8;
      uint32_t ah[4], al[4];
      tfsplit(Qs[r0 * QST + ko + t],     ah[0], al[0]);
      tfsplit(Qs[r1 * QST + ko + t],     ah[1], al[1]);
      tfsplit(Qs[r0 * QST + ko + t + 4], ah[2], al[2]);
      tfsplit(Qs[r1 * QST + ko + t + 4], ah[3], al[3]);
#pragma unroll
      for (int jb = 0; jb < 4; jb++) {
        int nr = wn * 32 + jb * 8 + g;
        uint32_t bh2[2] = { __float_as_uint(Kh[nr * KST + ko + t]),
                            __float_as_uint(Kh[nr * KST + ko + t + 4]) };
        uint32_t bl2[2] = { __float_as_uint(Kl[nr * KST + ko + t]),
                            __float_as_uint(Kl[nr * KST + ko + t + 4]) };
        mma_tf32(sacc[jb], ah, bh2);
        mma_tf32(sacc[jb], ah, bl2);
        mma_tf32(sacc[jb], al, bh2);
      }
    }

    if (kt == qt) {   // causal mask (k0 == q0)
#pragma unroll
      for (int jb = 0; jb < 4; jb++) {
        int cb = wn * 32 + jb * 8 + 2 * t;
        if (cb     > r0) sacc[jb][0] = -1e30f;
        if (cb + 1 > r0) sacc[jb][1] = -1e30f;
        if (cb     > r1) sacc[jb][2] = -1e30f;
        if (cb + 1 > r1) sacc[jb][3] = -1e30f;
      }
    }

    // ---- online softmax ----
    float mo0 = row_m[r0], mo1 = row_m[r1];
    float px0 = -1e30f, px1 = -1e30f;
#pragma unroll
    for (int jb = 0; jb < 4; jb++) {
      px0 = fmaxf(px0, fmaxf(sacc[jb][0], sacc[jb][1]));
      px1 = fmaxf(px1, fmaxf(sacc[jb][2], sacc[jb][3]));
    }
    px0 = fmaxf(px0, __shfl_xor_sync(0xffffffffu, px0, 1));
    px0 = fmaxf(px0, __shfl_xor_sync(0xffffffffu, px0, 2));
    px1 = fmaxf(px1, __shfl_xor_sync(0xffffffffu, px1, 1));
    px1 = fmaxf(px1, __shfl_xor_sync(0xffffffffu, px1, 2));
    if (t == 0) { pmax[r0 * 2 + wn] = px0; pmax[r1 * 2 + wn] = px1; }
    __syncthreads();

    float mn0 = fmaxf(mo0, fmaxf(pmax[r0 * 2], pmax[r0 * 2 + 1]));
    float mn1 = fmaxf(mo1, fmaxf(pmax[r1 * 2], pmax[r1 * 2 + 1]));
    float s0 = 0.f, s1 = 0.f;
#pragma unroll
    for (int jb = 0; jb < 4; jb++) {
      float p0 = __expf(sacc[jb][0] - mn0);
      float p1 = __expf(sacc[jb][1] - mn0);
      float p2 = __expf(sacc[jb][2] - mn1);
      float p3 = __expf(sacc[jb][3] - mn1);
      int cb = wn * 32 + jb * 8 + 2 * t;
      *(float2*)&Ps[r0 * PST + cb] = make_float2(p0, p1);
      *(float2*)&Ps[r1 * PST + cb] = make_float2(p2, p3);
      s0 += p0 + p1; s1 += p2 + p3;
    }
    s0 += __shfl_xor_sync(0xffffffffu, s0, 1);
    s0 += __shfl_xor_sync(0xffffffffu, s0, 2);
    s1 += __shfl_xor_sync(0xffffffffu, s1, 1);
    s1 += __shfl_xor_sync(0xffffffffu, s1, 2);
    if (t == 0) {
      psum[r0 * 2 + wn] = s0; psum[r1 * 2 + wn] = s1;
      if (wn == 0) {
        row_c[r0] = __expf(mo0 - mn0); row_m[r0] = mn0;
        row_c[r1] = __expf(mo1 - mn1); row_m[r1] = mn1;
      }
    }
    __syncthreads();

    if (wn == 0 && t == 0) {
      row_l[r0] = row_l[r0] * row_c[r0] + psum[r0 * 2] + psum[r0 * 2 + 1];
      row_l[r1] = row_l[r1] * row_c[r1] + psum[r1 * 2] + psum[r1 * 2 + 1];
    }

    // ---- PV: O = corr*O + P @ V (3xTF32) ----
    {
      float c0 = row_c[r0], c1 = row_c[r1];
#pragma unroll
      for (int jb = 0; jb < 8; jb++) {
        oacc[jb][0] *= c0; oacc[jb][1] *= c0;
        oacc[jb][2] *= c1; oacc[jb][3] *= c1;
      }
    }
    for (int kk = 0; kk < 8; kk++) {
      const int ko = kk * 8;
      uint32_t ah[4], al[4];
      tfsplit(Ps[r0 * PST + ko + t],     ah[0], al[0]);
      tfsplit(Ps[r1 * PST + ko + t],     ah[1], al[1]);
      tfsplit(Ps[r0 * PST + ko + t + 4], ah[2], al[2]);
      tfsplit(Ps[r1 * PST + ko + t + 4], ah[3], al[3]);
#pragma unroll
      for (int jb = 0; jb < 8; jb++) {
        int nr = wn * 64 + jb * 8 + g;
        uint32_t vh0, vl0, vh1, vl1;
        tfsplit(Vt[nr * VTS + ko + t],     vh0, vl0);
        tfsplit(Vt[nr * VTS + ko + t + 4], vh1, vl1);
        uint32_t bh2[2] = {vh0, vh1}, bl2[2] = {vl0, vl1};
        mma_tf32(oacc[jb], ah, bh2);
        mma_tf32(oacc[jb], ah, bl2);
        mma_tf32(oacc[jb], al, bh2);
      }
    }
    __syncthreads();
  }

  // epilogue
  float inv0 = 1.f / row_l[r0], inv1 = 1.f / row_l[r1];
#pragma unroll
  for (int jb = 0; jb < 8; jb++) {
    int col = h * VD + wn * 64 + jb * 8 + 2 * t;
    *(float2*)&g_attn[(size_t)(rowbase + q0 + r0) * (NH * VD) + col] =
        make_float2(oacc[jb][0] * inv0, oacc[jb][1] * inv0);
    *(float2*)&g_attn[(size_t)(rowbase + q0 + r1) * (NH * VD) + col] =
        make_float2(oacc[jb][2] * inv1, oacc[jb][3] * inv1);
  }
}

// ---------------- launcher ----------------
extern "C" void kernel_launch(void* const* d_in, const int* in_sizes, int n_in,
                              void* d_out, int out_size)
{
  const float *x = nullptr, *wq = nullptr, *wkv_a = nullptr, *kvnw = nullptr,
              *wkv_b = nullptr, *wo = nullptr, *fcos = nullptr, *fsin = nullptr;
  for (int i = 0; i < n_in; i++) {
    const float* p = (const float*)d_in[i];
    switch (in_sizes[i]) {
      case 8388608: x = p; break;
      case 6291456: wq = p; break;
      case 1179648: wkv_a = p; break;
      case 512:     kvnw = p; break;
      case 2097152: wkv_b = p; break;
      case 4194304: wo = p; break;
      case 65536:   if (!fcos) fcos = p; else fsin = p; break;
      default: break;
    }
  }
  float* out = (float*)d_out;

  float *p_q, *p_kv, *p_kvc, *p_kvb, *p_attn;
  cudaGetSymbolAddress((void**)&p_q,    g_q);
  cudaGetSymbolAddress((void**)&p_kv,   g_kv);
  cudaGetSymbolAddress((void**)&p_kvc,  g_kvc);
  cudaGetSymbolAddress((void**)&p_kvb,  g_kvb);
  cudaGetSymbolAddress((void**)&p_attn, g_attn);

  double mm = 0.1 * log(40.0) + 1.0;
  float scale = (float)((1.0 / sqrt(192.0)) * mm * mm);

  const size_t gsmem = (size_t)(2 * 128 * GST) * sizeof(uint32_t);
  cudaFuncSetAttribute(tgemm_nt, cudaFuncAttributeMaxDynamicSharedMemorySize, (int)gsmem);

  tgemm_nt<<<dim3(QOUT / 128, ROWS / 128), 256, gsmem>>>(x, wq, p_q, ROWS, QOUT, DIM);
  tgemm_nt<<<dim3((KVA + 127) / 128, ROWS / 128), 256, gsmem>>>(x, wkv_a, p_kv, ROWS, KVA, DIM);
  kv_post_kernel<<<ROWS, 128>>>(kvnw, fcos, fsin);
  tgemm_nt<<<dim3(KVB / 128, ROWS / 128), 256, gsmem>>>(p_kvc, wkv_b, p_kvb, ROWS, KVB, KV_LORA);
  {
    size_t smem = (size_t)(64 * QST + 2 * 64 * KST + 128 * VTS + 64 * PST + 128 + 128 + 192)
                  * sizeof(float);   // ~205 KB
    cudaFuncSetAttribute(attn_kernel, cudaFuncAttributeMaxDynamicSharedMemorySize, (int)smem);
    attn_kernel<<<dim3(SEQ / 64, Bsz * NH), 256, smem>>>(scale);
  }
  tgemm_nt<<<dim3(DIM / 128, ROWS / 128), 256, gsmem>>>(p_attn, wo, out, ROWS, DIM, NH * VD);
}

// round 8
// speedup vs baseline: 3.2174x; 1.8008x over previous
#include <cuda_runtime.h>
#include <cmath>
#include <cstdint>

#define Bsz 2
#define SEQ 2048
#define DIM 2048
#define NH 16
#define KV_LORA 512
#define NOPE 128
#define ROPE_D 64
#define VD 128
#define QKD 192
#define ROWS (Bsz*SEQ)
#define QOUT (NH*QKD)        // 3072
#define KVA (KV_LORA+ROPE_D) // 576
#define KVB (NH*(NOPE+VD))   // 4096

// ---------------- scratch ----------------
__device__ float g_q[(size_t)ROWS*QOUT];
__device__ float g_kv[(size_t)ROWS*KVA];
__device__ float g_kvc[(size_t)ROWS*KV_LORA];     // tf32-rounded
__device__ float g_kpe[(size_t)ROWS*ROPE_D];
__device__ float g_kvb[(size_t)ROWS*KVB];
__device__ float g_attn[(size_t)ROWS*(NH*VD)];    // tf32-rounded
// pre-rounded GEMM inputs
__device__ float g_xr[(size_t)ROWS*DIM];
__device__ float g_wqr[(size_t)QOUT*DIM];
__device__ float g_wkvar[(size_t)KVA*DIM];
__device__ float g_wkvbr[(size_t)KVB*KV_LORA];
__device__ float g_wor[(size_t)DIM*(NH*VD)];
// packed attention operands
__device__ float g_kh[(size_t)Bsz*NH*SEQ*QKD];    // tf32 K rows per (b,h)
__device__ float g_vh[(size_t)Bsz*NH*VD*SEQ];     // tf32 hi of V, transposed [c][s]
__device__ float g_vl[(size_t)Bsz*NH*VD*SEQ];     // tf32 lo of V, transposed

// ---------------- helpers ----------------
__device__ __forceinline__ uint32_t f2tf(float x) {
  uint32_t y;
  asm("cvt.rna.tf32.f32 %0, %1;" : "=r"(y) : "f"(x));
  return y;
}
__device__ __forceinline__ float uif(uint32_t x) { return __uint_as_float(x); }
__device__ __forceinline__ void tfsplit(float x, uint32_t& hi, uint32_t& lo) {
  hi = f2tf(x);
  lo = f2tf(x - __uint_as_float(hi));
}
__device__ __forceinline__ void mma_tf32(float* c, const uint32_t* a, const uint32_t* b) {
  asm volatile(
      "mma.sync.aligned.m16n8k8.row.col.f32.tf32.tf32.f32 "
      "{%0,%1,%2,%3}, {%4,%5,%6,%7}, {%8,%9}, {%0,%1,%2,%3};\n"
      : "+f"(c[0]), "+f"(c[1]), "+f"(c[2]), "+f"(c[3])
      : "r"(a[0]), "r"(a[1]), "r"(a[2]), "r"(a[3]), "r"(b[0]), "r"(b[1]));
}
__device__ __forceinline__ void cpa16(void* dst, const void* src, bool p) {
  uint32_t d = (uint32_t)__cvta_generic_to_shared(dst);
  int sz = p ? 16 : 0;
  asm volatile("cp.async.cg.shared.global [%0], [%1], 16, %2;" :: "r"(d), "l"(src), "r"(sz));
}
#define CP_COMMIT asm volatile("cp.async.commit_group;")
#define CP_WAIT0 asm volatile("cp.async.wait_group 0;")
#define CP_WAIT1 asm volatile("cp.async.wait_group 1;")

// ---------------- tf32 pre-round ----------------
__global__ void round_k(const float* __restrict__ s, float* __restrict__ d, int n) {
  int i = (blockIdx.x * blockDim.x + threadIdx.x) * 4;
  if (i < n) {
    float4 v = *(const float4*)(s + i);
    *(float4*)(d + i) = make_float4(uif(f2tf(v.x)), uif(f2tf(v.y)),
                                    uif(f2tf(v.z)), uif(f2tf(v.w)));
  }
}

// ---------------- tf32 GEMM, cp.async double-buffered ----------------
#define GST 36
__global__ __launch_bounds__(256) void tgemm_nt(
    const float* __restrict__ A, const float* __restrict__ B, float* __restrict__ C,
    int M, int N, int K)
{
  extern __shared__ float gsm[];
  const int tid = threadIdx.x;
  const int m0 = blockIdx.y * 128;
  const int n0 = blockIdx.x * 128;
  const int lane = tid & 31, warp = tid >> 5;
  const int g = lane >> 2, t = lane & 3;
  const int wm = warp >> 2, wn = warp & 3;
  const int lrow = tid >> 3;
  const int lc16 = (tid & 7) * 4;

  float acc[4][4][4];
#pragma unroll
  for (int i = 0; i < 4; i++)
#pragma unroll
    for (int j = 0; j < 4; j++)
#pragma unroll
      for (int r = 0; r < 4; r++) acc[i][j][r] = 0.f;

  const int nk = K / 32;

  auto issue = [&](int k0, int stg) {
    float* as = gsm + stg * (128 * GST);
    float* bs = gsm + 2 * (128 * GST) + stg * (128 * GST);
#pragma unroll
    for (int it = 0; it < 4; it++) {
      int row = lrow + it * 32;
      cpa16(&as[row * GST + lc16], A + (size_t)(m0 + row) * K + k0 + lc16, true);
      int bn = n0 + row;
      cpa16(&bs[row * GST + lc16], B + (size_t)bn * K + k0 + lc16, bn < N);
    }
    CP_COMMIT;
  };

  issue(0, 0);
  for (int i = 0; i < nk; i++) {
    if (i + 1 < nk) { issue((i + 1) * 32, (i + 1) & 1); CP_WAIT1; }
    else CP_WAIT0;
    __syncthreads();
    const float* as = gsm + (i & 1) * (128 * GST);
    const float* bs = gsm + 2 * (128 * GST) + (i & 1) * (128 * GST);
#pragma unroll
    for (int ks = 0; ks < 4; ks++) {
      const int kk = ks * 8;
      uint32_t af[4][4];
#pragma unroll
      for (int ii = 0; ii < 4; ii++) {
        int base = (wm * 64 + ii * 16 + g) * GST + kk + t;
        af[ii][0] = __float_as_uint(as[base]);
        af[ii][1] = __float_as_uint(as[base + 8 * GST]);
        af[ii][2] = __float_as_uint(as[base + 4]);
        af[ii][3] = __float_as_uint(as[base + 8 * GST + 4]);
      }
      uint32_t bf[4][2];
#pragma unroll
      for (int j = 0; j < 4; j++) {
        int base = (wn * 32 + j * 8 + g) * GST + kk + t;
        bf[j][0] = __float_as_uint(bs[base]);
        bf[j][1] = __float_as_uint(bs[base + 4]);
      }
#pragma unroll
      for (int ii = 0; ii < 4; ii++)
#pragma unroll
        for (int j = 0; j < 4; j++) mma_tf32(acc[ii][j], af[ii], bf[j]);
    }
    __syncthreads();
  }

#pragma unroll
  for (int i = 0; i < 4; i++) {
    int row  = m0 + wm * 64 + i * 16 + g;
    int row2 = row + 8;
#pragma unroll
    for (int j = 0; j < 4; j++) {
      int col = n0 + wn * 32 + j * 8 + 2 * t;
      if (col < N) {
        *(float2*)&C[(size_t)row  * N + col] = make_float2(acc[i][j][0], acc[i][j][1]);
        *(float2*)&C[(size_t)row2 * N + col] = make_float2(acc[i][j][2], acc[i][j][3]);
      }
    }
  }
}

// ---------------- rmsnorm(kv_c, rounded) + rotary(k_pe) ----------------
__global__ __launch_bounds__(128) void kv_post_kernel(
    const float* __restrict__ w, const float* __restrict__ fc, const float* __restrict__ fs)
{
  int row = blockIdx.x;
  const float* kv = g_kv + (size_t)row * KVA;
  int t = threadIdx.x;
  float local[4];
  float ss = 0.f;
#pragma unroll
  for (int i = 0; i < 4; i++) { float v = kv[t + 128 * i]; local[i] = v; ss += v * v; }
#pragma unroll
  for (int o = 16; o >= 1; o >>= 1) ss += __shfl_xor_sync(0xffffffffu, ss, o);
  __shared__ float warp_ss[4];
  if ((t & 31) == 0) warp_ss[t >> 5] = ss;
  __syncthreads();
  float tot = warp_ss[0] + warp_ss[1] + warp_ss[2] + warp_ss[3];
  float norm = rsqrtf(tot * (1.f / 512.f) + 1e-6f);
#pragma unroll
  for (int i = 0; i < 4; i++)
    g_kvc[(size_t)row * KV_LORA + t + 128 * i] = uif(f2tf(local[i] * norm * w[t + 128 * i]));

  if (t < 32) {
    int s = row & (SEQ - 1);
    float c  = fc[s * 32 + t];
    float sn = fs[s * 32 + t];
    float re = kv[KV_LORA + 2 * t], im = kv[KV_LORA + 2 * t + 1];
    g_kpe[(size_t)row * ROPE_D + 2 * t]     = re * c - im * sn;
    g_kpe[(size_t)row * ROPE_D + 2 * t + 1] = re * sn + im * c;
  }
}

// ---------------- pack K (rounded) per (b,h) ----------------
__global__ void prep_kh_kernel() {
  size_t i = (size_t)blockIdx.x * 256 + threadIdx.x;
  if (i >= (size_t)Bsz * NH * SEQ * QKD) return;
  int c = (int)(i % QKD);
  size_t t2 = i / QKD;
  int s = (int)(t2 % SEQ);
  int bh = (int)(t2 / SEQ);
  int b = bh >> 4, h = bh & 15;
  float v = (c < NOPE)
      ? g_kvb[((size_t)(b * SEQ + s)) * KVB + h * 256 + c]
      : g_kpe[((size_t)(b * SEQ + s)) * ROPE_D + (c - NOPE)];
  g_kh[i] = uif(f2tf(v));
}

// ---------------- pack V transposed, hi/lo split ----------------
__global__ void prep_v_kernel() {
  __shared__ float tile[32][33];
  int bh = blockIdx.z, b = bh >> 4, h = bh & 15;
  int s0 = blockIdx.x * 32, c0 = blockIdx.y * 32;
  int tx = threadIdx.x & 31, ty = threadIdx.x >> 5;   // 32 x 8
#pragma unroll
  for (int i = 0; i < 4; i++) {
    int s = s0 + ty + i * 8;
    tile[ty + i * 8][tx] = g_kvb[((size_t)(b * SEQ + s)) * KVB + h * 256 + 128 + c0 + tx];
  }
  __syncthreads();
#pragma unroll
  for (int i = 0; i < 4; i++) {
    int c = c0 + ty + i * 8;
    float v = tile[tx][ty + i * 8];
    uint32_t hb = f2tf(v);
    size_t o = ((size_t)bh * VD + c) * SEQ + s0 + tx;
    g_vh[o] = uif(hb);
    g_vl[o] = uif(f2tf(v - uif(hb)));
  }
}

// ---------------- pipelined tensor-core causal flash attention ----------------
#define QST 196
#define KST 196
#define VTS 68
#define PST 68
__global__ __launch_bounds__(256) void attn_kernel(float scale)
{
  extern __shared__ float sm[];
  float* Qs    = sm;                  // 64*196
  float* Kh    = Qs + 64 * QST;       // 64*196
  float* Vh    = Kh + 64 * KST;       // 128*68
  float* Vl    = Vh + 128 * VTS;      // 128*68
  float* Ps    = Vl + 128 * VTS;      // 64*68
  float* pmax  = Ps + 64 * PST;       // 128
  float* psum  = pmax + 128;          // 128
  float* row_m = psum + 128;          // 64
  float* row_l = row_m + 64;          // 64
  float* row_c = row_l + 64;          // 64

  const int qt = blockIdx.x, bh = blockIdx.y;
  const int b = bh >> 4;
  const int tid = threadIdx.x;
  const int lane = tid & 31, warp = tid >> 5;
  const int g = lane >> 2, t = lane & 3;
  const int wm = warp & 3, wn = warp >> 2;
  const int rowbase = b * SEQ, q0 = qt * 64;
  const int r0 = wm * 16 + g, r1 = r0 + 8;

  const float* khg = g_kh + (size_t)bh * SEQ * QKD;
  const float* vhg = g_vh + (size_t)bh * VD * SEQ;
  const float* vlg = g_vl + (size_t)bh * VD * SEQ;

  // K tile: 64 rows x 192 floats = 3072 16B-chunks (48 per row)
  auto issueK = [&](int k0) {
#pragma unroll
    for (int it = 0; it < 12; it++) {
      int ch = tid + it * 256;
      int r = ch / 48, cc = ch - r * 48;          // cc in [0,48)
      cpa16(&Kh[r * KST + cc * 4], khg + (size_t)(k0 + r) * QKD + cc * 4, true);
    }
    CP_COMMIT;
  };
  // V tiles: 128 rows x 64 floats = 2048 chunks each (16 per row)
  auto issueV = [&](int k0) {
#pragma unroll
    for (int it = 0; it < 8; it++) {
      int ch = tid + it * 256;
      int c = ch >> 4, cc = ch & 15;              // cc in [0,16)
      cpa16(&Vh[c * VTS + cc * 4], vhg + (size_t)c * SEQ + k0 + cc * 4, true);
      cpa16(&Vl[c * VTS + cc * 4], vlg + (size_t)c * SEQ + k0 + cc * 4, true);
    }
    CP_COMMIT;
  };

  if (tid < 64) { row_m[tid] = -1e30f; row_l[tid] = 0.f; }

  issueK(0);
  issueV(0);

  // Q tile (scaled fp32; reference's q-rotary is dead code -> raw projection)
  for (int idx = tid; idx < 64 * QKD; idx += 256) {
    int r = idx / QKD, c = idx - r * QKD;
    Qs[r * QST + c] = g_q[(size_t)(rowbase + q0 + r) * QOUT + (bh & 15) * QKD + c] * scale;
  }

  float oacc[8][4];
#pragma unroll
  for (int j = 0; j < 8; j++)
#pragma unroll
    for (int r = 0; r < 4; r++) oacc[j][r] = 0.f;

  for (int kt = 0; kt <= qt; kt++) {
    CP_WAIT1;                 // Kh(kt) done (V(kt) may pend)
    __syncthreads();

    // ---- scores: 2-term (Qhi+Qlo) x Khi ----
    float sacc[4][4];
#pragma unroll
    for (int j = 0; j < 4; j++)
#pragma unroll
      for (int r = 0; r < 4; r++) sacc[j][r] = 0.f;

#pragma unroll 4
    for (int kk = 0; kk < QKD / 8; kk++) {
      const int ko = kk * 8;
      uint32_t ah[4], al[4];
      tfsplit(Qs[r0 * QST + ko + t],     ah[0], al[0]);
      tfsplit(Qs[r1 * QST + ko + t],     ah[1], al[1]);
      tfsplit(Qs[r0 * QST + ko + t + 4], ah[2], al[2]);
      tfsplit(Qs[r1 * QST + ko + t + 4], ah[3], al[3]);
#pragma unroll
      for (int jb = 0; jb < 4; jb++) {
        int nr = wn * 32 + jb * 8 + g;
        uint32_t bh2[2] = { __float_as_uint(Kh[nr * KST + ko + t]),
                            __float_as_uint(Kh[nr * KST + ko + t + 4]) };
        mma_tf32(sacc[jb], ah, bh2);
        mma_tf32(sacc[jb], al, bh2);
      }
    }

    if (kt == qt) {
#pragma unroll
      for (int jb = 0; jb < 4; jb++) {
        int cb = wn * 32 + jb * 8 + 2 * t;
        if (cb     > r0) sacc[jb][0] = -1e30f;
        if (cb + 1 > r0) sacc[jb][1] = -1e30f;
        if (cb     > r1) sacc[jb][2] = -1e30f;
        if (cb + 1 > r1) sacc[jb][3] = -1e30f;
      }
    }

    // ---- online softmax ----
    float mo0 = row_m[r0], mo1 = row_m[r1];
    float px0 = -1e30f, px1 = -1e30f;
#pragma unroll
    for (int jb = 0; jb < 4; jb++) {
      px0 = fmaxf(px0, fmaxf(sacc[jb][0], sacc[jb][1]));
      px1 = fmaxf(px1, fmaxf(sacc[jb][2], sacc[jb][3]));
    }
    px0 = fmaxf(px0, __shfl_xor_sync(0xffffffffu, px0, 1));
    px0 = fmaxf(px0, __shfl_xor_sync(0xffffffffu, px0, 2));
    px1 = fmaxf(px1, __shfl_xor_sync(0xffffffffu, px1, 1));
    px1 = fmaxf(px1, __shfl_xor_sync(0xffffffffu, px1, 2));
    if (t == 0) { pmax[r0 * 2 + wn] = px0; pmax[r1 * 2 + wn] = px1; }
    __syncthreads();           // all warps done reading Kh

    float mn0 = fmaxf(mo0, fmaxf(pmax[r0 * 2], pmax[r0 * 2 + 1]));
    float mn1 = fmaxf(mo1, fmaxf(pmax[r1 * 2], pmax[r1 * 2 + 1]));
    float s0 = 0.f, s1 = 0.f;
#pragma unroll
    for (int jb = 0; jb < 4; jb++) {
      float p0 = __expf(sacc[jb][0] - mn0);
      float p1 = __expf(sacc[jb][1] - mn0);
      float p2 = __expf(sacc[jb][2] - mn1);
      float p3 = __expf(sacc[jb][3] - mn1);
      int cb = wn * 32 + jb * 8 + 2 * t;
      *(float2*)&Ps[r0 * PST + cb] = make_float2(p0, p1);
      *(float2*)&Ps[r1 * PST + cb] = make_float2(p2, p3);
      s0 += p0 + p1; s1 += p2 + p3;
    }
    s0 += __shfl_xor_sync(0xffffffffu, s0, 1);
    s0 += __shfl_xor_sync(0xffffffffu, s0, 2);
    s1 += __shfl_xor_sync(0xffffffffu, s1, 1);
    s1 += __shfl_xor_sync(0xffffffffu, s1, 2);
    if (t == 0) {
      psum[r0 * 2 + wn] = s0; psum[r1 * 2 + wn] = s1;
      if (wn == 0) {
        row_c[r0] = __expf(mo0 - mn0); row_m[r0] = mn0;
        row_c[r1] = __expf(mo1 - mn1); row_m[r1] = mn1;
      }
    }
    __syncthreads();

    // Kh free -> prefetch next K; then wait V(kt)
    if (kt < qt) { issueK((kt + 1) * 64); CP_WAIT1; }
    else CP_WAIT0;
    __syncthreads();

    if (wn == 0 && t == 0) {
      row_l[r0] = row_l[r0] * row_c[r0] + psum[r0 * 2] + psum[r0 * 2 + 1];
      row_l[r1] = row_l[r1] * row_c[r1] + psum[r1 * 2] + psum[r1 * 2 + 1];
    }

    // ---- PV: P x (Vhi + Vlo) ----
    {
      float c0 = row_c[r0], c1 = row_c[r1];
#pragma unroll
      for (int jb = 0; jb < 8; jb++) {
        oacc[jb][0] *= c0; oacc[jb][1] *= c0;
        oacc[jb][2] *= c1; oacc[jb][3] *= c1;
      }
    }
#pragma unroll 2
    for (int kk = 0; kk < 8; kk++) {
      const int ko = kk * 8;
      uint32_t ah[4];
      ah[0] = f2tf(Ps[r0 * PST + ko + t]);
      ah[1] = f2tf(Ps[r1 * PST + ko + t]);
      ah[2] = f2tf(Ps[r0 * PST + ko + t + 4]);
      ah[3] = f2tf(Ps[r1 * PST + ko + t + 4]);
#pragma unroll
      for (int jb = 0; jb < 8; jb++) {
        int nr = wn * 64 + jb * 8 + g;
        uint32_t bh2[2] = { __float_as_uint(Vh[nr * VTS + ko + t]),
                            __float_as_uint(Vh[nr * VTS + ko + t + 4]) };
        uint32_t bl2[2] = { __float_as_uint(Vl[nr * VTS + ko + t]),
                            __float_as_uint(Vl[nr * VTS + ko + t + 4]) };
        mma_tf32(oacc[jb], ah, bh2);
        mma_tf32(oacc[jb], ah, bl2);
      }
    }
    __syncthreads();           // all warps done reading Vh/Vl/Ps

    if (kt < qt) issueV((kt + 1) * 64);
  }

  // epilogue (store tf32-rounded; consumed by pre-rounded wo GEMM)
  float inv0 = 1.f / row_l[r0], inv1 = 1.f / row_l[r1];
#pragma unroll
  for (int jb = 0; jb < 8; jb++) {
    int col = (bh & 15) * VD + wn * 64 + jb * 8 + 2 * t;
    *(float2*)&g_attn[(size_t)(rowbase + q0 + r0) * (NH * VD) + col] =
        make_float2(uif(f2tf(oacc[jb][0] * inv0)), uif(f2tf(oacc[jb][1] * inv0)));
    *(float2*)&g_attn[(size_t)(rowbase + q0 + r1) * (NH * VD) + col] =
        make_float2(uif(f2tf(oacc[jb][2] * inv1)), uif(f2tf(oacc[jb][3] * inv1)));
  }
}

// ---------------- launcher ----------------
extern "C" void kernel_launch(void* const* d_in, const int* in_sizes, int n_in,
                              void* d_out, int out_size)
{
  const float *x = nullptr, *wq = nullptr, *wkv_a = nullptr, *kvnw = nullptr,
              *wkv_b = nullptr, *wo = nullptr, *fcos = nullptr, *fsin = nullptr;
  for (int i = 0; i < n_in; i++) {
    const float* p = (const float*)d_in[i];
    switch (in_sizes[i]) {
      case 8388608: x = p; break;
      case 6291456: wq = p; break;
      case 1179648: wkv_a = p; break;
      case 512:     kvnw = p; break;
      case 2097152: wkv_b = p; break;
      case 4194304: wo = p; break;
      case 65536:   if (!fcos) fcos = p; else fsin = p; break;
      default: break;
    }
  }
  float* out = (float*)d_out;

  float *p_q, *p_kvc, *p_attn, *p_xr, *p_wqr, *p_wkvar, *p_wkvbr, *p_wor, *p_kv, *p_kvb;
  cudaGetSymbolAddress((void**)&p_q,     g_q);
  cudaGetSymbolAddress((void**)&p_kv,    g_kv);
  cudaGetSymbolAddress((void**)&p_kvc,   g_kvc);
  cudaGetSymbolAddress((void**)&p_kvb,   g_kvb);
  cudaGetSymbolAddress((void**)&p_attn,  g_attn);
  cudaGetSymbolAddress((void**)&p_xr,    g_xr);
  cudaGetSymbolAddress((void**)&p_wqr,   g_wqr);
  cudaGetSymbolAddress((void**)&p_wkvar, g_wkvar);
  cudaGetSymbolAddress((void**)&p_wkvbr, g_wkvbr);
  cudaGetSymbolAddress((void**)&p_wor,   g_wor);

  double mm = 0.1 * log(40.0) + 1.0;
  float scale = (float)((1.0 / sqrt(192.0)) * mm * mm);

  auto rnd = [&](const float* s, float* d, int n) {
    round_k<<<(n / 4 + 255) / 256, 256>>>(s, d, n);
  };
  rnd(x,     p_xr,    ROWS * DIM);
  rnd(wq,    p_wqr,   QOUT * DIM);
  rnd(wkv_a, p_wkvar, KVA * DIM);
  rnd(wkv_b, p_wkvbr, KVB * KV_LORA);
  rnd(wo,    p_wor,   DIM * NH * VD);

  const size_t gsmem = (size_t)(4 * 128 * GST) * sizeof(float);   // 73728 B
  cudaFuncSetAttribute(tgemm_nt, cudaFuncAttributeMaxDynamicSharedMemorySize, (int)gsmem);

  tgemm_nt<<<dim3(QOUT / 128, ROWS / 128), 256, gsmem>>>(p_xr, p_wqr, p_q, ROWS, QOUT, DIM);
  tgemm_nt<<<dim3((KVA + 127) / 128, ROWS / 128), 256, gsmem>>>(p_xr, p_wkvar, p_kv, ROWS, KVA, DIM);
  kv_post_kernel<<<ROWS, 128>>>(kvnw, fcos, fsin);
  tgemm_nt<<<dim3(KVB / 128, ROWS / 128), 256, gsmem>>>(p_kvc, p_wkvbr, p_kvb, ROWS, KVB, KV_LORA);
  {
    size_t nkh = (size_t)Bsz * NH * SEQ * QKD;
    prep_kh_kernel<<<(unsigned)((nkh + 255) / 256), 256>>>();
    prep_v_kernel<<<dim3(SEQ / 32, VD / 32, Bsz * NH), 256>>>();
  }
  {
    size_t smem = (size_t)(64 * QST + 64 * KST + 2 * 128 * VTS + 64 * PST + 128 + 128 + 192)
                  * sizeof(float);   // ~189 KB
    cudaFuncSetAttribute(attn_kernel, cudaFuncAttributeMaxDynamicSharedMemorySize, (int)smem);
    attn_kernel<<<dim3(SEQ / 64, Bsz * NH), 256, smem>>>(scale);
  }
  tgemm_nt<<<dim3(DIM / 128, ROWS / 128), 256, gsmem>>>(p_attn, p_wor, out, ROWS, DIM, NH * VD);
}

// round 9
// speedup vs baseline: 3.3996x; 1.0566x over previous
#include <cuda_runtime.h>
#include <cmath>
#include <cstdint>

#define Bsz 2
#define SEQ 2048
#define DIM 2048
#define NH 16
#define KV_LORA 512
#define NOPE 128
#define ROPE_D 64
#define VD 128
#define QKD 192
#define ROWS (Bsz*SEQ)
#define QOUT (NH*QKD)        // 3072
#define KVA (KV_LORA+ROPE_D) // 576
#define KVB (NH*(NOPE+VD))   // 4096
#define NQT (SEQ/64)         // 32 query tiles

// ---------------- scratch ----------------
__device__ float g_q[(size_t)ROWS*QOUT];
__device__ float g_kv[(size_t)ROWS*KVA];
__device__ float g_kvc[(size_t)ROWS*KV_LORA];     // tf32-rounded
__device__ float g_kpe[(size_t)ROWS*ROPE_D];
__device__ float g_kvb[(size_t)ROWS*KVB];
__device__ float g_attn[(size_t)ROWS*(NH*VD)];    // tf32-rounded
// pre-rounded GEMM inputs
__device__ float g_xr[(size_t)ROWS*DIM];
__device__ float g_wqr[(size_t)QOUT*DIM];
__device__ float g_wkvar[(size_t)KVA*DIM];
__device__ float g_wkvbr[(size_t)KVB*KV_LORA];
__device__ float g_wor[(size_t)DIM*(NH*VD)];
// packed attention operands
__device__ float g_kh[(size_t)Bsz*NH*SEQ*QKD];    // tf32 K rows per (b,h)
__device__ float g_vh[(size_t)Bsz*NH*VD*SEQ];     // tf32 hi of V, transposed [c][s]
__device__ float g_vl[(size_t)Bsz*NH*VD*SEQ];     // tf32 lo of V, transposed

// ---------------- helpers ----------------
__device__ __forceinline__ uint32_t f2tf(float x) {
  uint32_t y;
  asm("cvt.rna.tf32.f32 %0, %1;" : "=r"(y) : "f"(x));
  return y;
}
__device__ __forceinline__ float uif(uint32_t x) { return __uint_as_float(x); }
__device__ __forceinline__ void tfsplit(float x, uint32_t& hi, uint32_t& lo) {
  hi = f2tf(x);
  lo = f2tf(x - __uint_as_float(hi));
}
__device__ __forceinline__ void mma_tf32(float* c, const uint32_t* a, const uint32_t* b) {
  asm volatile(
      "mma.sync.aligned.m16n8k8.row.col.f32.tf32.tf32.f32 "
      "{%0,%1,%2,%3}, {%4,%5,%6,%7}, {%8,%9}, {%0,%1,%2,%3};\n"
      : "+f"(c[0]), "+f"(c[1]), "+f"(c[2]), "+f"(c[3])
      : "r"(a[0]), "r"(a[1]), "r"(a[2]), "r"(a[3]), "r"(b[0]), "r"(b[1]));
}
__device__ __forceinline__ void cpa16(void* dst, const void* src, bool p) {
  uint32_t d = (uint32_t)__cvta_generic_to_shared(dst);
  int sz = p ? 16 : 0;
  asm volatile("cp.async.cg.shared.global [%0], [%1], 16, %2;" :: "r"(d), "l"(src), "r"(sz));
}
#define CP_COMMIT asm volatile("cp.async.commit_group;")
#define CP_WAIT0 asm volatile("cp.async.wait_group 0;")
#define CP_WAIT1 asm volatile("cp.async.wait_group 1;")

// ---------------- tf32 pre-round ----------------
__global__ void round_k(const float* __restrict__ s, float* __restrict__ d, int n) {
  int i = (blockIdx.x * blockDim.x + threadIdx.x) * 4;
  if (i < n) {
    float4 v = *(const float4*)(s + i);
    *(float4*)(d + i) = make_float4(uif(f2tf(v.x)), uif(f2tf(v.y)),
                                    uif(f2tf(v.z)), uif(f2tf(v.w)));
  }
}

// ---------------- tf32 GEMM, cp.async double-buffered, 2 CTAs/SM ----------------
#define GST 36
__global__ __launch_bounds__(256, 2) void tgemm_nt(
    const float* __restrict__ A, const float* __restrict__ B, float* __restrict__ C,
    int M, int N, int K)
{
  extern __shared__ float gsm[];
  const int tid = threadIdx.x;
  const int m0 = blockIdx.y * 128;
  const int n0 = blockIdx.x * 128;
  const int lane = tid & 31, warp = tid >> 5;
  const int g = lane >> 2, t = lane & 3;
  const int wm = warp >> 2, wn = warp & 3;
  const int lrow = tid >> 3;
  const int lc16 = (tid & 7) * 4;

  float acc[4][4][4];
#pragma unroll
  for (int i = 0; i < 4; i++)
#pragma unroll
    for (int j = 0; j < 4; j++)
#pragma unroll
      for (int r = 0; r < 4; r++) acc[i][j][r] = 0.f;

  const int nk = K / 32;

  auto issue = [&](int k0, int stg) {
    float* as = gsm + stg * (128 * GST);
    float* bs = gsm + 2 * (128 * GST) + stg * (128 * GST);
#pragma unroll
    for (int it = 0; it < 4; it++) {
      int row = lrow + it * 32;
      cpa16(&as[row * GST + lc16], A + (size_t)(m0 + row) * K + k0 + lc16, true);
      int bn = n0 + row;
      cpa16(&bs[row * GST + lc16], B + (size_t)bn * K + k0 + lc16, bn < N);
    }
    CP_COMMIT;
  };

  issue(0, 0);
  for (int i = 0; i < nk; i++) {
    if (i + 1 < nk) { issue((i + 1) * 32, (i + 1) & 1); CP_WAIT1; }
    else CP_WAIT0;
    __syncthreads();
    const float* as = gsm + (i & 1) * (128 * GST);
    const float* bs = gsm + 2 * (128 * GST) + (i & 1) * (128 * GST);
#pragma unroll
    for (int ks = 0; ks < 4; ks++) {
      const int kk = ks * 8;
      uint32_t af[4][4];
#pragma unroll
      for (int ii = 0; ii < 4; ii++) {
        int base = (wm * 64 + ii * 16 + g) * GST + kk + t;
        af[ii][0] = __float_as_uint(as[base]);
        af[ii][1] = __float_as_uint(as[base + 8 * GST]);
        af[ii][2] = __float_as_uint(as[base + 4]);
        af[ii][3] = __float_as_uint(as[base + 8 * GST + 4]);
      }
      uint32_t bf[4][2];
#pragma unroll
      for (int j = 0; j < 4; j++) {
        int base = (wn * 32 + j * 8 + g) * GST + kk + t;
        bf[j][0] = __float_as_uint(bs[base]);
        bf[j][1] = __float_as_uint(bs[base + 4]);
      }
#pragma unroll
      for (int ii = 0; ii < 4; ii++)
#pragma unroll
        for (int j = 0; j < 4; j++) mma_tf32(acc[ii][j], af[ii], bf[j]);
    }
    __syncthreads();
  }

#pragma unroll
  for (int i = 0; i < 4; i++) {
    int row  = m0 + wm * 64 + i * 16 + g;
    int row2 = row + 8;
#pragma unroll
    for (int j = 0; j < 4; j++) {
      int col = n0 + wn * 32 + j * 8 + 2 * t;
      if (col < N) {
        *(float2*)&C[(size_t)row  * N + col] = make_float2(acc[i][j][0], acc[i][j][1]);
        *(float2*)&C[(size_t)row2 * N + col] = make_float2(acc[i][j][2], acc[i][j][3]);
      }
    }
  }
}

// ---------------- rmsnorm(kv_c, rounded) + rotary(k_pe) ----------------
__global__ __launch_bounds__(128) void kv_post_kernel(
    const float* __restrict__ w, const float* __restrict__ fc, const float* __restrict__ fs)
{
  int row = blockIdx.x;
  const float* kv = g_kv + (size_t)row * KVA;
  int t = threadIdx.x;
  float local[4];
  float ss = 0.f;
#pragma unroll
  for (int i = 0; i < 4; i++) { float v = kv[t + 128 * i]; local[i] = v; ss += v * v; }
#pragma unroll
  for (int o = 16; o >= 1; o >>= 1) ss += __shfl_xor_sync(0xffffffffu, ss, o);
  __shared__ float warp_ss[4];
  if ((t & 31) == 0) warp_ss[t >> 5] = ss;
  __syncthreads();
  float tot = warp_ss[0] + warp_ss[1] + warp_ss[2] + warp_ss[3];
  float norm = rsqrtf(tot * (1.f / 512.f) + 1e-6f);
#pragma unroll
  for (int i = 0; i < 4; i++)
    g_kvc[(size_t)row * KV_LORA + t + 128 * i] = uif(f2tf(local[i] * norm * w[t + 128 * i]));

  if (t < 32) {
    int s = row & (SEQ - 1);
    float c  = fc[s * 32 + t];
    float sn = fs[s * 32 + t];
    float re = kv[KV_LORA + 2 * t], im = kv[KV_LORA + 2 * t + 1];
    g_kpe[(size_t)row * ROPE_D + 2 * t]     = re * c - im * sn;
    g_kpe[(size_t)row * ROPE_D + 2 * t + 1] = re * sn + im * c;
  }
}

// ---------------- pack K (rounded) per (b,h) ----------------
__global__ void prep_kh_kernel() {
  size_t i = (size_t)blockIdx.x * 256 + threadIdx.x;
  if (i >= (size_t)Bsz * NH * SEQ * QKD) return;
  int c = (int)(i % QKD);
  size_t t2 = i / QKD;
  int s = (int)(t2 % SEQ);
  int bh = (int)(t2 / SEQ);
  int b = bh >> 4, h = bh & 15;
  float v = (c < NOPE)
      ? g_kvb[((size_t)(b * SEQ + s)) * KVB + h * 256 + c]
      : g_kpe[((size_t)(b * SEQ + s)) * ROPE_D + (c - NOPE)];
  g_kh[i] = uif(f2tf(v));
}

// ---------------- pack V transposed, hi/lo split ----------------
__global__ void prep_v_kernel() {
  __shared__ float tile[32][33];
  int bh = blockIdx.z, b = bh >> 4, h = bh & 15;
  int s0 = blockIdx.x * 32, c0 = blockIdx.y * 32;
  int tx = threadIdx.x & 31, ty = threadIdx.x >> 5;   // 32 x 8
#pragma unroll
  for (int i = 0; i < 4; i++) {
    int s = s0 + ty + i * 8;
    tile[ty + i * 8][tx] = g_kvb[((size_t)(b * SEQ + s)) * KVB + h * 256 + 128 + c0 + tx];
  }
  __syncthreads();
#pragma unroll
  for (int i = 0; i < 4; i++) {
    int c = c0 + ty + i * 8;
    float v = tile[tx][ty + i * 8];
    uint32_t hb = f2tf(v);
    size_t o = ((size_t)bh * VD + c) * SEQ + s0 + tx;
    g_vh[o] = uif(hb);
    g_vl[o] = uif(f2tf(v - uif(hb)));
  }
}

// ---------------- pipelined tensor-core causal flash attention ----------------
// Work-balanced: grid (NQT/2, 32). CTA x handles q-tiles x and NQT-1-x,
// so every CTA does exactly NQT+1 = 33 tile iterations (no causal tail).
#define QST 196
#define KST 196
#define VTS 68
#define PST 68
__global__ __launch_bounds__(256) void attn_kernel(float scale)
{
  extern __shared__ float sm[];
  float* Qs    = sm;                  // 64*196
  float* Kh    = Qs + 64 * QST;       // 64*196
  float* Vh    = Kh + 64 * KST;       // 128*68
  float* Vl    = Vh + 128 * VTS;      // 128*68
  float* Ps    = Vl + 128 * VTS;      // 64*68
  float* pmax  = Ps + 64 * PST;       // 128
  float* psum  = pmax + 128;          // 128
  float* row_m = psum + 128;          // 64
  float* row_l = row_m + 64;          // 64
  float* row_c = row_l + 64;          // 64

  const int bh = blockIdx.y;
  const int b = bh >> 4;
  const int tid = threadIdx.x;
  const int lane = tid & 31, warp = tid >> 5;
  const int g = lane >> 2, t = lane & 3;
  const int wm = warp & 3, wn = warp >> 2;
  const int rowbase = b * SEQ;
  const int r0 = wm * 16 + g, r1 = r0 + 8;

  const float* khg = g_kh + (size_t)bh * SEQ * QKD;
  const float* vhg = g_vh + (size_t)bh * VD * SEQ;
  const float* vlg = g_vl + (size_t)bh * VD * SEQ;

  auto issueK = [&](int k0) {
#pragma unroll
    for (int it = 0; it < 12; it++) {
      int ch = tid + it * 256;
      int r = ch / 48, cc = ch - r * 48;
      cpa16(&Kh[r * KST + cc * 4], khg + (size_t)(k0 + r) * QKD + cc * 4, true);
    }
    CP_COMMIT;
  };
  auto issueV = [&](int k0) {
#pragma unroll
    for (int it = 0; it < 8; it++) {
      int ch = tid + it * 256;
      int c = ch >> 4, cc = ch & 15;
      cpa16(&Vh[c * VTS + cc * 4], vhg + (size_t)c * SEQ + k0 + cc * 4, true);
      cpa16(&Vl[c * VTS + cc * 4], vlg + (size_t)c * SEQ + k0 + cc * 4, true);
    }
    CP_COMMIT;
  };

  for (int seg = 0; seg < 2; seg++) {
    const int qt = seg == 0 ? blockIdx.x : (NQT - 1 - blockIdx.x);
    const int q0 = qt * 64;

    __syncthreads();          // prior segment fully done with smem state
    if (tid < 64) { row_m[tid] = -1e30f; row_l[tid] = 0.f; }

    issueK(0);
    issueV(0);

    // Q tile (scaled fp32; reference's q-rotary is dead code -> raw projection)
    for (int idx = tid; idx < 64 * QKD; idx += 256) {
      int r = idx / QKD, c = idx - r * QKD;
      Qs[r * QST + c] = g_q[(size_t)(rowbase + q0 + r) * QOUT + (bh & 15) * QKD + c] * scale;
    }

    float oacc[8][4];
#pragma unroll
    for (int j = 0; j < 8; j++)
#pragma unroll
      for (int r = 0; r < 4; r++) oacc[j][r] = 0.f;

    for (int kt = 0; kt <= qt; kt++) {
      CP_WAIT1;                 // Kh(kt) done (V(kt) may pend)
      __syncthreads();

      // ---- scores: 2-term (Qhi+Qlo) x Khi ----
      float sacc[4][4];
#pragma unroll
      for (int j = 0; j < 4; j++)
#pragma unroll
        for (int r = 0; r < 4; r++) sacc[j][r] = 0.f;

#pragma unroll 4
      for (int kk = 0; kk < QKD / 8; kk++) {
        const int ko = kk * 8;
        uint32_t ah[4], al[4];
        tfsplit(Qs[r0 * QST + ko + t],     ah[0], al[0]);
        tfsplit(Qs[r1 * QST + ko + t],     ah[1], al[1]);
        tfsplit(Qs[r0 * QST + ko + t + 4], ah[2], al[2]);
        tfsplit(Qs[r1 * QST + ko + t + 4], ah[3], al[3]);
#pragma unroll
        for (int jb = 0; jb < 4; jb++) {
          int nr = wn * 32 + jb * 8 + g;
          uint32_t bh2[2] = { __float_as_uint(Kh[nr * KST + ko + t]),
                              __float_as_uint(Kh[nr * KST + ko + t + 4]) };
          mma_tf32(sacc[jb], ah, bh2);
          mma_tf32(sacc[jb], al, bh2);
        }
      }

      if (kt == qt) {
#pragma unroll
        for (int jb = 0; jb < 4; jb++) {
          int cb = wn * 32 + jb * 8 + 2 * t;
          if (cb     > r0) sacc[jb][0] = -1e30f;
          if (cb + 1 > r0) sacc[jb][1] = -1e30f;
          if (cb     > r1) sacc[jb][2] = -1e30f;
          if (cb + 1 > r1) sacc[jb][3] = -1e30f;
        }
      }

      // ---- online softmax ----
      float mo0 = row_m[r0], mo1 = row_m[r1];
      float px0 = -1e30f, px1 = -1e30f;
#pragma unroll
      for (int jb = 0; jb < 4; jb++) {
        px0 = fmaxf(px0, fmaxf(sacc[jb][0], sacc[jb][1]));
        px1 = fmaxf(px1, fmaxf(sacc[jb][2], sacc[jb][3]));
      }
      px0 = fmaxf(px0, __shfl_xor_sync(0xffffffffu, px0, 1));
      px0 = fmaxf(px0, __shfl_xor_sync(0xffffffffu, px0, 2));
      px1 = fmaxf(px1, __shfl_xor_sync(0xffffffffu, px1, 1));
      px1 = fmaxf(px1, __shfl_xor_sync(0xffffffffu, px1, 2));
      if (t == 0) { pmax[r0 * 2 + wn] = px0; pmax[r1 * 2 + wn] = px1; }
      __syncthreads();           // all warps done reading Kh

      float mn0 = fmaxf(mo0, fmaxf(pmax[r0 * 2], pmax[r0 * 2 + 1]));
      float mn1 = fmaxf(mo1, fmaxf(pmax[r1 * 2], pmax[r1 * 2 + 1]));
      float s0 = 0.f, s1 = 0.f;
#pragma unroll
      for (int jb = 0; jb < 4; jb++) {
        float p0 = __expf(sacc[jb][0] - mn0);
        float p1 = __expf(sacc[jb][1] - mn0);
        float p2 = __expf(sacc[jb][2] - mn1);
        float p3 = __expf(sacc[jb][3] - mn1);
        int cb = wn * 32 + jb * 8 + 2 * t;
        *(float2*)&Ps[r0 * PST + cb] = make_float2(p0, p1);
        *(float2*)&Ps[r1 * PST + cb] = make_float2(p2, p3);
        s0 += p0 + p1; s1 += p2 + p3;
      }
      s0 += __shfl_xor_sync(0xffffffffu, s0, 1);
      s0 += __shfl_xor_sync(0xffffffffu, s0, 2);
      s1 += __shfl_xor_sync(0xffffffffu, s1, 1);
      s1 += __shfl_xor_sync(0xffffffffu, s1, 2);
      if (t == 0) {
        psum[r0 * 2 + wn] = s0; psum[r1 * 2 + wn] = s1;
        if (wn == 0) {
          row_c[r0] = __expf(mo0 - mn0); row_m[r0] = mn0;
          row_c[r1] = __expf(mo1 - mn1); row_m[r1] = mn1;
        }
      }
      __syncthreads();

      // Kh free -> prefetch next K; then wait V(kt)
      if (kt < qt) { issueK((kt + 1) * 64); CP_WAIT1; }
      else CP_WAIT0;
      __syncthreads();

      if (wn == 0 && t == 0) {
        row_l[r0] = row_l[r0] * row_c[r0] + psum[r0 * 2] + psum[r0 * 2 + 1];
        row_l[r1] = row_l[r1] * row_c[r1] + psum[r1 * 2] + psum[r1 * 2 + 1];
      }

      // ---- PV: P x (Vhi + Vlo) ----
      {
        float c0 = row_c[r0], c1 = row_c[r1];
#pragma unroll
        for (int jb = 0; jb < 8; jb++) {
          oacc[jb][0] *= c0; oacc[jb][1] *= c0;
          oacc[jb][2] *= c1; oacc[jb][3] *= c1;
        }
      }
#pragma unroll 2
      for (int kk = 0; kk < 8; kk++) {
        const int ko = kk * 8;
        uint32_t ah[4];
        ah[0] = f2tf(Ps[r0 * PST + ko + t]);
        ah[1] = f2tf(Ps[r1 * PST + ko + t]);
        ah[2] = f2tf(Ps[r0 * PST + ko + t + 4]);
        ah[3] = f2tf(Ps[r1 * PST + ko + t + 4]);
#pragma unroll
        for (int jb = 0; jb < 8; jb++) {
          int nr = wn * 64 + jb * 8 + g;
          uint32_t bh2[2] = { __float_as_uint(Vh[nr * VTS + ko + t]),
                              __float_as_uint(Vh[nr * VTS + ko + t + 4]) };
          uint32_t bl2[2] = { __float_as_uint(Vl[nr * VTS + ko + t]),
                              __float_as_uint(Vl[nr * VTS + ko + t + 4]) };
          mma_tf32(oacc[jb], ah, bh2);
          mma_tf32(oacc[jb], ah, bl2);
        }
      }
      __syncthreads();           // all warps done reading Vh/Vl/Ps

      if (kt < qt) issueV((kt + 1) * 64);
    }

    // epilogue (store tf32-rounded; consumed by pre-rounded wo GEMM)
    float inv0 = 1.f / row_l[r0], inv1 = 1.f / row_l[r1];
#pragma unroll
    for (int jb = 0; jb < 8; jb++) {
      int col = (bh & 15) * VD + wn * 64 + jb * 8 + 2 * t;
      *(float2*)&g_attn[(size_t)(rowbase + q0 + r0) * (NH * VD) + col] =
          make_float2(uif(f2tf(oacc[jb][0] * inv0)), uif(f2tf(oacc[jb][1] * inv0)));
      *(float2*)&g_attn[(size_t)(rowbase + q0 + r1) * (NH * VD) + col] =
          make_float2(uif(f2tf(oacc[jb][2] * inv1)), uif(f2tf(oacc[jb][3] * inv1)));
    }
  }
}

// ---------------- launcher ----------------
extern "C" void kernel_launch(void* const* d_in, const int* in_sizes, int n_in,
                              void* d_out, int out_size)
{
  const float *x = nullptr, *wq = nullptr, *wkv_a = nullptr, *kvnw = nullptr,
              *wkv_b = nullptr, *wo = nullptr, *fcos = nullptr, *fsin = nullptr;
  for (int i = 0; i < n_in; i++) {
    const float* p = (const float*)d_in[i];
    switch (in_sizes[i]) {
      case 8388608: x = p; break;
      case 6291456: wq = p; break;
      case 1179648: wkv_a = p; break;
      case 512:     kvnw = p; break;
      case 2097152: wkv_b = p; break;
      case 4194304: wo = p; break;
      case 65536:   if (!fcos) fcos = p; else fsin = p; break;
      default: break;
    }
  }
  float* out = (float*)d_out;

  float *p_q, *p_kvc, *p_attn, *p_xr, *p_wqr, *p_wkvar, *p_wkvbr, *p_wor, *p_kv, *p_kvb;
  cudaGetSymbolAddress((void**)&p_q,     g_q);
  cudaGetSymbolAddress((void**)&p_kv,    g_kv);
  cudaGetSymbolAddress((void**)&p_kvc,   g_kvc);
  cudaGetSymbolAddress((void**)&p_kvb,   g_kvb);
  cudaGetSymbolAddress((void**)&p_attn,  g_attn);
  cudaGetSymbolAddress((void**)&p_xr,    g_xr);
  cudaGetSymbolAddress((void**)&p_wqr,   g_wqr);
  cudaGetSymbolAddress((void**)&p_wkvar, g_wkvar);
  cudaGetSymbolAddress((void**)&p_wkvbr, g_wkvbr);
  cudaGetSymbolAddress((void**)&p_wor,   g_wor);

  double mm = 0.1 * log(40.0) + 1.0;
  float scale = (float)((1.0 / sqrt(192.0)) * mm * mm);

  auto rnd = [&](const float* s, float* d, int n) {
    round_k<<<(n / 4 + 255) / 256, 256>>>(s, d, n);
  };
  rnd(x,     p_xr,    ROWS * DIM);
  rnd(wq,    p_wqr,   QOUT * DIM);
  rnd(wkv_a, p_wkvar, KVA * DIM);
  rnd(wkv_b, p_wkvbr, KVB * KV_LORA);
  rnd(wo,    p_wor,   DIM * NH * VD);

  const size_t gsmem = (size_t)(4 * 128 * GST) * sizeof(float);   // 73728 B
  cudaFuncSetAttribute(tgemm_nt, cudaFuncAttributeMaxDynamicSharedMemorySize, (int)gsmem);

  tgemm_nt<<<dim3(QOUT / 128, ROWS / 128), 256, gsmem>>>(p_xr, p_wqr, p_q, ROWS, QOUT, DIM);
  tgemm_nt<<<dim3((KVA + 127) / 128, ROWS / 128), 256, gsmem>>>(p_xr, p_wkvar, p_kv, ROWS, KVA, DIM);
  kv_post_kernel<<<ROWS, 128>>>(kvnw, fcos, fsin);
  tgemm_nt<<<dim3(KVB / 128, ROWS / 128), 256, gsmem>>>(p_kvc, p_wkvbr, p_kvb, ROWS, KVB, KV_LORA);
  {
    size_t nkh = (size_t)Bsz * NH * SEQ * QKD;
    prep_kh_kernel<<<(unsigned)((nkh + 255) / 256), 256>>>();
    prep_v_kernel<<<dim3(SEQ / 32, VD / 32, Bsz * NH), 256>>>();
  }
  {
    size_t smem = (size_t)(64 * QST + 64 * KST + 2 * 128 * VTS + 64 * PST + 128 + 128 + 192)
                  * sizeof(float);   // ~189 KB
    cudaFuncSetAttribute(attn_kernel, cudaFuncAttributeMaxDynamicSharedMemorySize, (int)smem);
    attn_kernel<<<dim3(NQT / 2, Bsz * NH), 256, smem>>>(scale);
  }
  tgemm_nt<<<dim3(DIM / 128, ROWS / 128), 256, gsmem>>>(p_attn, p_wor, out, ROWS, DIM, NH * VD);
}

// round 13
// speedup vs baseline: 3.9963x; 1.1755x over previous
#include <cuda_runtime.h>
#include <cmath>
#include <cstdint>

#define Bsz 2
#define SEQ 2048
#define DIM 2048
#define NH 16
#define KV_LORA 512
#define NOPE 128
#define ROPE_D 64
#define VD 128
#define QKD 192
#define ROWS (Bsz*SEQ)
#define QOUT (NH*QKD)        // 3072
#define KVA (KV_LORA+ROPE_D) // 576
#define KVB (NH*(NOPE+VD))   // 4096
#define BM 128               // q rows per attention CTA
#define NQT2 (SEQ/BM)        // 16 q tiles

// ---------------- scratch ----------------
__device__ float g_q[(size_t)ROWS*QOUT];
__device__ float g_kv[(size_t)ROWS*KVA];
__device__ float g_kvc[(size_t)ROWS*KV_LORA];     // tf32-rounded
__device__ float g_kpe[(size_t)ROWS*ROPE_D];
__device__ float g_kvb[(size_t)ROWS*KVB];
__device__ float g_attn[(size_t)ROWS*(NH*VD)];    // tf32-rounded
// pre-rounded GEMM inputs
__device__ float g_xr[(size_t)ROWS*DIM];
__device__ float g_wqr[(size_t)QOUT*DIM];
__device__ float g_wkvar[(size_t)KVA*DIM];
__device__ float g_wkvbr[(size_t)KVB*KV_LORA];
__device__ float g_wor[(size_t)DIM*(NH*VD)];
// packed attention operands
__device__ float g_kh[(size_t)Bsz*NH*SEQ*QKD];    // tf32 K rows per (b,h)
__device__ float g_vh[(size_t)Bsz*NH*VD*SEQ];     // tf32 V, transposed [c][s]

// ---------------- helpers ----------------
__device__ __forceinline__ uint32_t f2tf(float x) {
  uint32_t y;
  asm("cvt.rna.tf32.f32 %0, %1;" : "=r"(y) : "f"(x));
  return y;
}
__device__ __forceinline__ float uif(uint32_t x) { return __uint_as_float(x); }
__device__ __forceinline__ void tfsplit(float x, uint32_t& hi, uint32_t& lo) {
  hi = f2tf(x);
  lo = f2tf(x - __uint_as_float(hi));
}
__device__ __forceinline__ void mma_tf32(float* c, const uint32_t* a, const uint32_t* b) {
  asm volatile(
      "mma.sync.aligned.m16n8k8.row.col.f32.tf32.tf32.f32 "
      "{%0,%1,%2,%3}, {%4,%5,%6,%7}, {%8,%9}, {%0,%1,%2,%3};\n"
      : "+f"(c[0]), "+f"(c[1]), "+f"(c[2]), "+f"(c[3])
      : "r"(a[0]), "r"(a[1]), "r"(a[2]), "r"(a[3]), "r"(b[0]), "r"(b[1]));
}
__device__ __forceinline__ void cpa16(void* dst, const void* src, bool p) {
  uint32_t d = (uint32_t)__cvta_generic_to_shared(dst);
  int sz = p ? 16 : 0;
  asm volatile("cp.async.cg.shared.global [%0], [%1], 16, %2;" :: "r"(d), "l"(src), "r"(sz));
}
#define CP_COMMIT asm volatile("cp.async.commit_group;")
#define CP_WAIT0 asm volatile("cp.async.wait_group 0;")
#define CP_WAIT1 asm volatile("cp.async.wait_group 1;")

// ---------------- tf32 pre-round ----------------
__global__ void round_k(const float* __restrict__ s, float* __restrict__ d, int n) {
  int i = (blockIdx.x * blockDim.x + threadIdx.x) * 4;
  if (i < n) {
    float4 v = *(const float4*)(s + i);
    *(float4*)(d + i) = make_float4(uif(f2tf(v.x)), uif(f2tf(v.y)),
                                    uif(f2tf(v.z)), uif(f2tf(v.w)));
  }
}

// ---------------- tf32 GEMM, cp.async double-buffered, 2 CTAs/SM ----------------
#define GST 36
__global__ __launch_bounds__(256, 2) void tgemm_nt(
    const float* __restrict__ A, const float* __restrict__ B, float* __restrict__ C,
    int M, int N, int K)
{
  extern __shared__ float gsm[];
  const int tid = threadIdx.x;
  const int m0 = blockIdx.y * 128;
  const int n0 = blockIdx.x * 128;
  const int lane = tid & 31, warp = tid >> 5;
  const int g = lane >> 2, t = lane & 3;
  const int wm = warp >> 2, wn = warp & 3;
  const int lrow = tid >> 3;
  const int lc16 = (tid & 7) * 4;

  float acc[4][4][4];
#pragma unroll
  for (int i = 0; i < 4; i++)
#pragma unroll
    for (int j = 0; j < 4; j++)
#pragma unroll
      for (int r = 0; r < 4; r++) acc[i][j][r] = 0.f;

  const int nk = K / 32;

  auto issue = [&](int k0, int stg) {
    float* as = gsm + stg * (128 * GST);
    float* bs = gsm + 2 * (128 * GST) + stg * (128 * GST);
#pragma unroll
    for (int it = 0; it < 4; it++) {
      int row = lrow + it * 32;
      cpa16(&as[row * GST + lc16], A + (size_t)(m0 + row) * K + k0 + lc16, true);
      int bn = n0 + row;
      cpa16(&bs[row * GST + lc16], B + (size_t)bn * K + k0 + lc16, bn < N);
    }
    CP_COMMIT;
  };

  issue(0, 0);
  for (int i = 0; i < nk; i++) {
    if (i + 1 < nk) { issue((i + 1) * 32, (i + 1) & 1); CP_WAIT1; }
    else CP_WAIT0;
    __syncthreads();
    const float* as = gsm + (i & 1) * (128 * GST);
    const float* bs = gsm + 2 * (128 * GST) + (i & 1) * (128 * GST);
#pragma unroll
    for (int ks = 0; ks < 4; ks++) {
      const int kk = ks * 8;
      uint32_t af[4][4];
#pragma unroll
      for (int ii = 0; ii < 4; ii++) {
        int base = (wm * 64 + ii * 16 + g) * GST + kk + t;
        af[ii][0] = __float_as_uint(as[base]);
        af[ii][1] = __float_as_uint(as[base + 8 * GST]);
        af[ii][2] = __float_as_uint(as[base + 4]);
        af[ii][3] = __float_as_uint(as[base + 8 * GST + 4]);
      }
      uint32_t bf[4][2];
#pragma unroll
      for (int j = 0; j < 4; j++) {
        int base = (wn * 32 + j * 8 + g) * GST + kk + t;
        bf[j][0] = __float_as_uint(bs[base]);
        bf[j][1] = __float_as_uint(bs[base + 4]);
      }
#pragma unroll
      for (int ii = 0; ii < 4; ii++)
#pragma unroll
        for (int j = 0; j < 4; j++) mma_tf32(acc[ii][j], af[ii], bf[j]);
    }
    __syncthreads();
  }

#pragma unroll
  for (int i = 0; i < 4; i++) {
    int row  = m0 + wm * 64 + i * 16 + g;
    int row2 = row + 8;
#pragma unroll
    for (int j = 0; j < 4; j++) {
      int col = n0 + wn * 32 + j * 8 + 2 * t;
      if (col < N) {
        *(float2*)&C[(size_t)row  * N + col] = make_float2(acc[i][j][0], acc[i][j][1]);
        *(float2*)&C[(size_t)row2 * N + col] = make_float2(acc[i][j][2], acc[i][j][3]);
      }
    }
  }
}

// ---------------- rmsnorm(kv_c, rounded) + rotary(k_pe) ----------------
__global__ __launch_bounds__(128) void kv_post_kernel(
    const float* __restrict__ w, const float* __restrict__ fc, const float* __restrict__ fs)
{
  int row = blockIdx.x;
  const float* kv = g_kv + (size_t)row * KVA;
  int t = threadIdx.x;
  float local[4];
  float ss = 0.f;
#pragma unroll
  for (int i = 0; i < 4; i++) { float v = kv[t + 128 * i]; local[i] = v; ss += v * v; }
#pragma unroll
  for (int o = 16; o >= 1; o >>= 1) ss += __shfl_xor_sync(0xffffffffu, ss, o);
  __shared__ float warp_ss[4];
  if ((t & 31) == 0) warp_ss[t >> 5] = ss;
  __syncthreads();
  float tot = warp_ss[0] + warp_ss[1] + warp_ss[2] + warp_ss[3];
  float norm = rsqrtf(tot * (1.f / 512.f) + 1e-6f);
#pragma unroll
  for (int i = 0; i < 4; i++)
    g_kvc[(size_t)row * KV_LORA + t + 128 * i] = uif(f2tf(local[i] * norm * w[t + 128 * i]));

  if (t < 32) {
    int s = row & (SEQ - 1);
    float c  = fc[s * 32 + t];
    float sn = fs[s * 32 + t];
    float re = kv[KV_LORA + 2 * t], im = kv[KV_LORA + 2 * t + 1];
    g_kpe[(size_t)row * ROPE_D + 2 * t]     = re * c - im * sn;
    g_kpe[(size_t)row * ROPE_D + 2 * t + 1] = re * sn + im * c;
  }
}

// ---------------- pack K (rounded) per (b,h) ----------------
__global__ void prep_kh_kernel() {
  size_t i = (size_t)blockIdx.x * 256 + threadIdx.x;
  if (i >= (size_t)Bsz * NH * SEQ * QKD) return;
  int c = (int)(i % QKD);
  size_t t2 = i / QKD;
  int s = (int)(t2 % SEQ);
  int bh = (int)(t2 / SEQ);
  int b = bh >> 4, h = bh & 15;
  float v = (c < NOPE)
      ? g_kvb[((size_t)(b * SEQ + s)) * KVB + h * 256 + c]
      : g_kpe[((size_t)(b * SEQ + s)) * ROPE_D + (c - NOPE)];
  g_kh[i] = uif(f2tf(v));
}

// ---------------- pack V transposed (tf32-rounded) ----------------
__global__ void prep_v_kernel() {
  __shared__ float tile[32][33];
  int bh = blockIdx.z, b = bh >> 4, h = bh & 15;
  int s0 = blockIdx.x * 32, c0 = blockIdx.y * 32;
  int tx = threadIdx.x & 31, ty = threadIdx.x >> 5;   // 32 x 8
#pragma unroll
  for (int i = 0; i < 4; i++) {
    int s = s0 + ty + i * 8;
    tile[ty + i * 8][tx] = g_kvb[((size_t)(b * SEQ + s)) * KVB + h * 256 + 128 + c0 + tx];
  }
  __syncthreads();
#pragma unroll
  for (int i = 0; i < 4; i++) {
    int c = c0 + ty + i * 8;
    float v = tile[tx][ty + i * 8];
    g_vh[((size_t)bh * VD + c) * SEQ + s0 + tx] = uif(f2tf(v));
  }
}

// ---------------- pipelined tensor-core causal flash attention ----------------
// BM=128 q-rows, BN=64 kv-rows, 512 threads = 16 warps (8 wm x 2 wn).
// Work-balanced: grid (NQT2/2, 32); CTA x does q-tiles x and 15-x -> 34 iters.
#define QST 196
#define KST 196
#define VTS 68
#define PST 68
__global__ __launch_bounds__(512) void attn_kernel(float scale)
{
  extern __shared__ float sm[];
  float* Qs    = sm;                  // 128*196
  float* Kh    = Qs + BM * QST;       // 64*196
  float* Vh    = Kh + 64 * KST;       // 128*68
  float* Ps    = Vh + 128 * VTS;      // 128*68
  float* pmax  = Ps + BM * PST;       // 256
  float* psum  = pmax + 256;          // 256
  float* row_m = psum + 256;          // 128
  float* row_l = row_m + 128;         // 128
  float* row_c = row_l + 128;         // 128

  const int bh = blockIdx.y;
  const int b = bh >> 4;
  const int tid = threadIdx.x;
  const int lane = tid & 31, warp = tid >> 5;
  const int g = lane >> 2, t = lane & 3;
  const int wm = warp >> 1, wn = warp & 1;
  const int rowbase = b * SEQ;
  const int r0 = wm * 16 + g, r1 = r0 + 8;

  const float* khg = g_kh + (size_t)bh * SEQ * QKD;
  const float* vhg = g_vh + (size_t)bh * VD * SEQ;

  auto issueK = [&](int k0) {
#pragma unroll
    for (int it = 0; it < 6; it++) {
      int ch = tid + it * 512;                    // 3072 chunks
      int r = ch / 48, cc = ch - r * 48;
      cpa16(&Kh[r * KST + cc * 4], khg + (size_t)(k0 + r) * QKD + cc * 4, true);
    }
    CP_COMMIT;
  };
  auto issueV = [&](int k0) {
#pragma unroll
    for (int it = 0; it < 4; it++) {
      int ch = tid + it * 512;                    // 2048 chunks
      int c = ch >> 4, cc = ch & 15;
      cpa16(&Vh[c * VTS + cc * 4], vhg + (size_t)c * SEQ + k0 + cc * 4, true);
    }
    CP_COMMIT;
  };

  for (int seg = 0; seg < 2; seg++) {
    const int qt = seg == 0 ? blockIdx.x : (NQT2 - 1 - blockIdx.x);
    const int q0 = qt * BM;
    const int nkt = 2 * qt + 2;

    __syncthreads();            // previous segment fully done with smem
    if (tid < 128) { row_m[tid] = -1e30f; row_l[tid] = 0.f; }

    issueK(0);
    issueV(0);

    // Q tile (scaled fp32; reference's q-rotary is dead code -> raw projection)
    for (int idx = tid; idx < BM * QKD / 4; idx += 512) {
      int r = idx / 48, c4 = (idx - r * 48) * 4;
      float4 v = *(const float4*)&g_q[(size_t)(rowbase + q0 + r) * QOUT + (bh & 15) * QKD + c4];
      *(float4*)&Qs[r * QST + c4] =
          make_float4(v.x * scale, v.y * scale, v.z * scale, v.w * scale);
    }

    float oacc[8][4];
#pragma unroll
    for (int j = 0; j < 8; j++)
#pragma unroll
      for (int r = 0; r < 4; r++) oacc[j][r] = 0.f;

    for (int kt = 0; kt < nkt; kt++) {
      const int k0 = kt * 64;
      CP_WAIT1;                 // Kh(kt) done (V(kt) may pend)
      __syncthreads();

      // ---- scores: 2-term (Qhi+Qlo) x Khi ----
      float sacc[4][4];
#pragma unroll
      for (int j = 0; j < 4; j++)
#pragma unroll
        for (int r = 0; r < 4; r++) sacc[j][r] = 0.f;

#pragma unroll 4
      for (int kk = 0; kk < QKD / 8; kk++) {
        const int ko = kk * 8;
        uint32_t ah[4], al[4];
        tfsplit(Qs[r0 * QST + ko + t],     ah[0], al[0]);
        tfsplit(Qs[r1 * QST + ko + t],     ah[1], al[1]);
        tfsplit(Qs[r0 * QST + ko + t + 4], ah[2], al[2]);
        tfsplit(Qs[r1 * QST + ko + t + 4], ah[3], al[3]);
#pragma unroll
        for (int jb = 0; jb < 4; jb++) {
          int nr = wn * 32 + jb * 8 + g;
          uint32_t bh2[2] = { __float_as_uint(Kh[nr * KST + ko + t]),
                              __float_as_uint(Kh[nr * KST + ko + t + 4]) };
          mma_tf32(sacc[jb], ah, bh2);
          mma_tf32(sacc[jb], al, bh2);
        }
      }

      if (kt >= 2 * qt) {       // diagonal-straddling tiles
#pragma unroll
        for (int jb = 0; jb < 4; jb++) {
          int cb = k0 + wn * 32 + jb * 8 + 2 * t;   // global col
          if (cb     > q0 + r0) sacc[jb][0] = -1e30f;
          if (cb + 1 > q0 + r0) sacc[jb][1] = -1e30f;
          if (cb     > q0 + r1) sacc[jb][2] = -1e30f;
          if (cb + 1 > q0 + r1) sacc[jb][3] = -1e30f;
        }
      }

      // ---- online softmax ----
      float mo0 = row_m[r0], mo1 = row_m[r1];
      float px0 = -1e30f, px1 = -1e30f;
#pragma unroll
      for (int jb = 0; jb < 4; jb++) {
        px0 = fmaxf(px0, fmaxf(sacc[jb][0], sacc[jb][1]));
        px1 = fmaxf(px1, fmaxf(sacc[jb][2], sacc[jb][3]));
      }
      px0 = fmaxf(px0, __shfl_xor_sync(0xffffffffu, px0, 1));
      px0 = fmaxf(px0, __shfl_xor_sync(0xffffffffu, px0, 2));
      px1 = fmaxf(px1, __shfl_xor_sync(0xffffffffu, px1, 1));
      px1 = fmaxf(px1, __shfl_xor_sync(0xffffffffu, px1, 2));
      if (t == 0) { pmax[r0 * 2 + wn] = px0; pmax[r1 * 2 + wn] = px1; }
      __syncthreads();           // all warps done reading Kh

      float mn0 = fmaxf(mo0, fmaxf(pmax[r0 * 2], pmax[r0 * 2 + 1]));
      float mn1 = fmaxf(mo1, fmaxf(pmax[r1 * 2], pmax[r1 * 2 + 1]));
      float s0 = 0.f, s1 = 0.f;
#pragma unroll
      for (int jb = 0; jb < 4; jb++) {
        float p0 = __expf(sacc[jb][0] - mn0);
        float p1 = __expf(sacc[jb][1] - mn0);
        float p2 = __expf(sacc[jb][2] - mn1);
        float p3 = __expf(sacc[jb][3] - mn1);
        int cb = wn * 32 + jb * 8 + 2 * t;
        *(float2*)&Ps[r0 * PST + cb] = make_float2(p0, p1);
        *(float2*)&Ps[r1 * PST + cb] = make_float2(p2, p3);
        s0 += p0 + p1; s1 += p2 + p3;
      }
      s0 += __shfl_xor_sync(0xffffffffu, s0, 1);
      s0 += __shfl_xor_sync(0xffffffffu, s0, 2);
      s1 += __shfl_xor_sync(0xffffffffu, s1, 1);
      s1 += __shfl_xor_sync(0xffffffffu, s1, 2);
      if (t == 0) {
        psum[r0 * 2 + wn] = s0; psum[r1 * 2 + wn] = s1;
        if (wn == 0) {
          row_c[r0] = __expf(mo0 - mn0); row_m[r0] = mn0;
          row_c[r1] = __expf(mo1 - mn1); row_m[r1] = mn1;
        }
      }
      __syncthreads();

      // Kh free -> prefetch next K; then wait V(kt)
      if (kt < nkt - 1) { issueK((kt + 1) * 64); CP_WAIT1; }
      else CP_WAIT0;
      __syncthreads();

      if (wn == 0 && t == 0) {
        row_l[r0] = row_l[r0] * row_c[r0] + psum[r0 * 2] + psum[r0 * 2 + 1];
        row_l[r1] = row_l[r1] * row_c[r1] + psum[r1 * 2] + psum[r1 * 2 + 1];
      }

      // ---- PV: P x Vhi ----
      {
        float c0 = row_c[r0], c1 = row_c[r1];
#pragma unroll
        for (int jb = 0; jb < 8; jb++) {
          oacc[jb][0] *= c0; oacc[jb][1] *= c0;
          oacc[jb][2] *= c1; oacc[jb][3] *= c1;
        }
      }
#pragma unroll 2
      for (int kk = 0; kk < 8; kk++) {
        const int ko = kk * 8;
        uint32_t ah[4];
        ah[0] = f2tf(Ps[r0 * PST + ko + t]);
        ah[1] = f2tf(Ps[r1 * PST + ko + t]);
        ah[2] = f2tf(Ps[r0 * PST + ko + t + 4]);
        ah[3] = f2tf(Ps[r1 * PST + ko + t + 4]);
#pragma unroll
        for (int jb = 0; jb < 8; jb++) {
          int nr = wn * 64 + jb * 8 + g;
          uint32_t bh2[2] = { __float_as_uint(Vh[nr * VTS + ko + t]),
                              __float_as_uint(Vh[nr * VTS + ko + t + 4]) };
          mma_tf32(oacc[jb], ah, bh2);
        }
      }
      __syncthreads();           // all warps done reading Vh/Ps

      if (kt < nkt - 1) issueV((kt + 1) * 64);
    }

    // epilogue (store tf32-rounded; consumed by pre-rounded wo GEMM)
    float inv0 = 1.f / row_l[r0], inv1 = 1.f / row_l[r1];
#pragma unroll
    for (int jb = 0; jb < 8; jb++) {
      int col = (bh & 15) * VD + wn * 64 + jb * 8 + 2 * t;
      *(float2*)&g_attn[(size_t)(rowbase + q0 + r0) * (NH * VD) + col] =
          make_float2(uif(f2tf(oacc[jb][0] * inv0)), uif(f2tf(oacc[jb][1] * inv0)));
      *(float2*)&g_attn[(size_t)(rowbase + q0 + r1) * (NH * VD) + col] =
          make_float2(uif(f2tf(oacc[jb][2] * inv1)), uif(f2tf(oacc[jb][3] * inv1)));
    }
  }
}

// ---------------- launcher ----------------
extern "C" void kernel_launch(void* const* d_in, const int* in_sizes, int n_in,
                              void* d_out, int out_size)
{
  const float *x = nullptr, *wq = nullptr, *wkv_a = nullptr, *kvnw = nullptr,
              *wkv_b = nullptr, *wo = nullptr, *fcos = nullptr, *fsin = nullptr;
  for (int i = 0; i < n_in; i++) {
    const float* p = (const float*)d_in[i];
    switch (in_sizes[i]) {
      case 8388608: x = p; break;
      case 6291456: wq = p; break;
      case 1179648: wkv_a = p; break;
      case 512:     kvnw = p; break;
      case 2097152: wkv_b = p; break;
      case 4194304: wo = p; break;
      case 65536:   if (!fcos) fcos = p; else fsin = p; break;
      default: break;
    }
  }
  float* out = (float*)d_out;

  float *p_q, *p_kvc, *p_attn, *p_xr, *p_wqr, *p_wkvar, *p_wkvbr, *p_wor, *p_kv, *p_kvb;
  cudaGetSymbolAddress((void**)&p_q,     g_q);
  cudaGetSymbolAddress((void**)&p_kv,    g_kv);
  cudaGetSymbolAddress((void**)&p_kvc,   g_kvc);
  cudaGetSymbolAddress((void**)&p_kvb,   g_kvb);
  cudaGetSymbolAddress((void**)&p_attn,  g_attn);
  cudaGetSymbolAddress((void**)&p_xr,    g_xr);
  cudaGetSymbolAddress((void**)&p_wqr,   g_wqr);
  cudaGetSymbolAddress((void**)&p_wkvar, g_wkvar);
  cudaGetSymbolAddress((void**)&p_wkvbr, g_wkvbr);
  cudaGetSymbolAddress((void**)&p_wor,   g_wor);

  double mm = 0.1 * log(40.0) + 1.0;
  float scale = (float)((1.0 / sqrt(192.0)) * mm * mm);

  auto rnd = [&](const float* s, float* d, int n) {
    round_k<<<(n / 4 + 255) / 256, 256>>>(s, d, n);
  };
  rnd(x,     p_xr,    ROWS * DIM);
  rnd(wq,    p_wqr,   QOUT * DIM);
  rnd(wkv_a, p_wkvar, KVA * DIM);
  rnd(wkv_b, p_wkvbr, KVB * KV_LORA);
  rnd(wo,    p_wor,   DIM * NH * VD);

  const size_t gsmem = (size_t)(4 * 128 * GST) * sizeof(float);   // 73728 B
  cudaFuncSetAttribute(tgemm_nt, cudaFuncAttributeMaxDynamicSharedMemorySize, (int)gsmem);

  tgemm_nt<<<dim3(QOUT / 128, ROWS / 128), 256, gsmem>>>(p_xr, p_wqr, p_q, ROWS, QOUT, DIM);
  tgemm_nt<<<dim3((KVA + 127) / 128, ROWS / 128), 256, gsmem>>>(p_xr, p_wkvar, p_kv, ROWS, KVA, DIM);
  kv_post_kernel<<<ROWS, 128>>>(kvnw, fcos, fsin);
  tgemm_nt<<<dim3(KVB / 128, ROWS / 128), 256, gsmem>>>(p_kvc, p_wkvbr, p_kvb, ROWS, KVB, KV_LORA);
  {
    size_t nkh = (size_t)Bsz * NH * SEQ * QKD;
    prep_kh_kernel<<<(unsigned)((nkh + 255) / 256), 256>>>();
    prep_v_kernel<<<dim3(SEQ / 32, VD / 32, Bsz * NH), 256>>>();
  }
  {
    size_t smem = (size_t)(BM * QST + 64 * KST + 128 * VTS + BM * PST + 256 + 256 + 384)
                  * sizeof(float);   // ~224 KB
    cudaFuncSetAttribute(attn_kernel, cudaFuncAttributeMaxDynamicSharedMemorySize, (int)smem);
    attn_kernel<<<dim3(NQT2 / 2, Bsz * NH), 512, smem>>>(scale);
  }
  tgemm_nt<<<dim3(DIM / 128, ROWS / 128), 256, gsmem>>>(p_attn, p_wor, out, ROWS, DIM, NH * VD);
}

// round 14
// speedup vs baseline: 4.3987x; 1.1007x over previous
#include <cuda_runtime.h>
#include <cmath>
#include <cstdint>

#define Bsz 2
#define SEQ 2048
#define DIM 2048
#define NH 16
#define KV_LORA 512
#define NOPE 128
#define ROPE_D 64
#define VD 128
#define QKD 192
#define ROWS (Bsz*SEQ)
#define QOUT (NH*QKD)        // 3072
#define KVA (KV_LORA+ROPE_D) // 576
#define KVB (NH*(NOPE+VD))   // 4096
#define BM 128               // q rows per attention work unit
#define NQT2 (SEQ/BM)        // 16 q tiles
#define NUNITS (NQT2*Bsz*NH) // 512 attention work units

// ---------------- scratch ----------------
__device__ float g_q[(size_t)ROWS*QOUT];
__device__ float g_kv[(size_t)ROWS*KVA];
__device__ float g_kvc[(size_t)ROWS*KV_LORA];     // tf32-rounded, k-permuted
__device__ float g_kpe[(size_t)ROWS*ROPE_D];
__device__ float g_kvb[(size_t)ROWS*KVB];
__device__ float g_attn[(size_t)ROWS*(NH*VD)];    // tf32-rounded, k-permuted
// pre-rounded + k-permuted GEMM inputs
__device__ float g_xr[(size_t)ROWS*DIM];
__device__ float g_wqr[(size_t)QOUT*DIM];
__device__ float g_wkvar[(size_t)KVA*DIM];
__device__ float g_wkvbr[(size_t)KVB*KV_LORA];
__device__ float g_wor[(size_t)DIM*(NH*VD)];
// packed attention operands (NOT permuted)
__device__ float g_kh[(size_t)Bsz*NH*SEQ*QKD];    // tf32 K rows per (b,h)
__device__ float g_vh[(size_t)Bsz*NH*VD*SEQ];     // tf32 V, transposed [c][s]
// dynamic scheduler counter
__device__ int g_ctr;

// ---------------- helpers ----------------
__device__ __forceinline__ uint32_t f2tf(float x) {
  uint32_t y;
  asm("cvt.rna.tf32.f32 %0, %1;" : "=r"(y) : "f"(x));
  return y;
}
__device__ __forceinline__ float uif(uint32_t x) { return __uint_as_float(x); }
__device__ __forceinline__ void tfsplit(float x, uint32_t& hi, uint32_t& lo) {
  hi = f2tf(x);
  lo = f2tf(x - __uint_as_float(hi));
}
// position of original k-index within the permuted-by-8 layout:
// stored[2j] = orig[j], stored[2j+1] = orig[j+4]
__device__ __forceinline__ int kperm(int k) {
  int k7 = k & 7;
  return (k & ~7) | ((k7 < 4) ? (k7 * 2) : ((k7 - 4) * 2 + 1));
}
__device__ __forceinline__ void mma_tf32(float* c, const uint32_t* a, const uint32_t* b) {
  asm volatile(
      "mma.sync.aligned.m16n8k8.row.col.f32.tf32.tf32.f32 "
      "{%0,%1,%2,%3}, {%4,%5,%6,%7}, {%8,%9}, {%0,%1,%2,%3};\n"
      : "+f"(c[0]), "+f"(c[1]), "+f"(c[2]), "+f"(c[3])
      : "r"(a[0]), "r"(a[1]), "r"(a[2]), "r"(a[3]), "r"(b[0]), "r"(b[1]));
}
__device__ __forceinline__ void cpa16(void* dst, const void* src, bool p) {
  uint32_t d = (uint32_t)__cvta_generic_to_shared(dst);
  int sz = p ? 16 : 0;
  asm volatile("cp.async.cg.shared.global [%0], [%1], 16, %2;" :: "r"(d), "l"(src), "r"(sz));
}
#define CP_COMMIT asm volatile("cp.async.commit_group;")
#define CP_WAIT0 asm volatile("cp.async.wait_group 0;")
#define CP_WAIT1 asm volatile("cp.async.wait_group 1;")

// ---------------- tf32 pre-round + k-permute (groups of 8) ----------------
__global__ void round_perm(const float* __restrict__ s, float* __restrict__ d, int n) {
  int i = (blockIdx.x * blockDim.x + threadIdx.x) * 8;
  if (i < n) {
    float4 a = *(const float4*)(s + i);       // orig k 0..3
    float4 b = *(const float4*)(s + i + 4);   // orig k 4..7
    float4 o0 = make_float4(uif(f2tf(a.x)), uif(f2tf(b.x)), uif(f2tf(a.y)), uif(f2tf(b.y)));
    float4 o1 = make_float4(uif(f2tf(a.z)), uif(f2tf(b.z)), uif(f2tf(a.w)), uif(f2tf(b.w)));
    *(float4*)(d + i)     = o0;
    *(float4*)(d + i + 4) = o1;
  }
}

__global__ void reset_ctr_kernel() { g_ctr = 0; }

// ---------------- tf32 GEMM, cp.async double-buffered, LDS.64 fragments ----------------
// Inputs A,B are tf32-rounded AND k-permuted-by-8.
#define GST 40
__global__ __launch_bounds__(256, 2) void tgemm_nt(
    const float* __restrict__ A, const float* __restrict__ B, float* __restrict__ C,
    int M, int N, int K)
{
  extern __shared__ float gsm[];
  const int tid = threadIdx.x;
  const int m0 = blockIdx.y * 128;
  const int n0 = blockIdx.x * 128;
  const int lane = tid & 31, warp = tid >> 5;
  const int g = lane >> 2, t = lane & 3;
  const int wm = warp >> 2, wn = warp & 3;
  const int lrow = tid >> 3;
  const int lc16 = (tid & 7) * 4;

  float acc[4][4][4];
#pragma unroll
  for (int i = 0; i < 4; i++)
#pragma unroll
    for (int j = 0; j < 4; j++)
#pragma unroll
      for (int r = 0; r < 4; r++) acc[i][j][r] = 0.f;

  const int nk = K / 32;

  auto issue = [&](int k0, int stg) {
    float* as = gsm + stg * (128 * GST);
    float* bs = gsm + 2 * (128 * GST) + stg * (128 * GST);
#pragma unroll
    for (int it = 0; it < 4; it++) {
      int row = lrow + it * 32;
      cpa16(&as[row * GST + lc16], A + (size_t)(m0 + row) * K + k0 + lc16, true);
      int bn = n0 + row;
      cpa16(&bs[row * GST + lc16], B + (size_t)bn * K + k0 + lc16, bn < N);
    }
    CP_COMMIT;
  };

  issue(0, 0);
  for (int i = 0; i < nk; i++) {
    if (i + 1 < nk) { issue((i + 1) * 32, (i + 1) & 1); CP_WAIT1; }
    else CP_WAIT0;
    __syncthreads();
    const float* as = gsm + (i & 1) * (128 * GST);
    const float* bs = gsm + 2 * (128 * GST) + (i & 1) * (128 * GST);
#pragma unroll
    for (int ks = 0; ks < 4; ks++) {
      const int kk = ks * 8;
      uint32_t af[4][4];
#pragma unroll
      for (int ii = 0; ii < 4; ii++) {
        int base = (wm * 64 + ii * 16 + g) * GST + kk + 2 * t;
        float2 a01 = *(const float2*)&as[base];              // orig k=t, t+4 (row)
        float2 a23 = *(const float2*)&as[base + 8 * GST];    // orig k=t, t+4 (row+8)
        af[ii][0] = __float_as_uint(a01.x);
        af[ii][1] = __float_as_uint(a23.x);
        af[ii][2] = __float_as_uint(a01.y);
        af[ii][3] = __float_as_uint(a23.y);
      }
      uint32_t bf[4][2];
#pragma unroll
      for (int j = 0; j < 4; j++) {
        int base = (wn * 32 + j * 8 + g) * GST + kk + 2 * t;
        float2 b01 = *(const float2*)&bs[base];
        bf[j][0] = __float_as_uint(b01.x);
        bf[j][1] = __float_as_uint(b01.y);
      }
#pragma unroll
      for (int ii = 0; ii < 4; ii++)
#pragma unroll
        for (int j = 0; j < 4; j++) mma_tf32(acc[ii][j], af[ii], bf[j]);
    }
    __syncthreads();
  }

#pragma unroll
  for (int i = 0; i < 4; i++) {
    int row  = m0 + wm * 64 + i * 16 + g;
    int row2 = row + 8;
#pragma unroll
    for (int j = 0; j < 4; j++) {
      int col = n0 + wn * 32 + j * 8 + 2 * t;
      if (col < N) {
        *(float2*)&C[(size_t)row  * N + col] = make_float2(acc[i][j][0], acc[i][j][1]);
        *(float2*)&C[(size_t)row2 * N + col] = make_float2(acc[i][j][2], acc[i][j][3]);
      }
    }
  }
}

// ---------------- rmsnorm(kv_c, rounded + permuted) + rotary(k_pe) ----------------
__global__ __launch_bounds__(128) void kv_post_kernel(
    const float* __restrict__ w, const float* __restrict__ fc, const float* __restrict__ fs)
{
  int row = blockIdx.x;
  const float* kv = g_kv + (size_t)row * KVA;
  int t = threadIdx.x;
  float local[4];
  float ss = 0.f;
#pragma unroll
  for (int i = 0; i < 4; i++) { float v = kv[t + 128 * i]; local[i] = v; ss += v * v; }
#pragma unroll
  for (int o = 16; o >= 1; o >>= 1) ss += __shfl_xor_sync(0xffffffffu, ss, o);
  __shared__ float warp_ss[4];
  if ((t & 31) == 0) warp_ss[t >> 5] = ss;
  __syncthreads();
  float tot = warp_ss[0] + warp_ss[1] + warp_ss[2] + warp_ss[3];
  float norm = rsqrtf(tot * (1.f / 512.f) + 1e-6f);
#pragma unroll
  for (int i = 0; i < 4; i++)
    g_kvc[(size_t)row * KV_LORA + kperm(t + 128 * i)] =
        uif(f2tf(local[i] * norm * w[t + 128 * i]));

  if (t < 32) {
    int s = row & (SEQ - 1);
    float c  = fc[s * 32 + t];
    float sn = fs[s * 32 + t];
    float re = kv[KV_LORA + 2 * t], im = kv[KV_LORA + 2 * t + 1];
    g_kpe[(size_t)row * ROPE_D + 2 * t]     = re * c - im * sn;
    g_kpe[(size_t)row * ROPE_D + 2 * t + 1] = re * sn + im * c;
  }
}

// ---------------- pack K (rounded) per (b,h) ----------------
__global__ void prep_kh_kernel() {
  size_t i = (size_t)blockIdx.x * 256 + threadIdx.x;
  if (i >= (size_t)Bsz * NH * SEQ * QKD) return;
  int c = (int)(i % QKD);
  size_t t2 = i / QKD;
  int s = (int)(t2 % SEQ);
  int bh = (int)(t2 / SEQ);
  int b = bh >> 4, h = bh & 15;
  float v = (c < NOPE)
      ? g_kvb[((size_t)(b * SEQ + s)) * KVB + h * 256 + c]
      : g_kpe[((size_t)(b * SEQ + s)) * ROPE_D + (c - NOPE)];
  g_kh[i] = uif(f2tf(v));
}

// ---------------- pack V transposed (tf32-rounded) ----------------
__global__ void prep_v_kernel() {
  __shared__ float tile[32][33];
  int bh = blockIdx.z, b = bh >> 4, h = bh & 15;
  int s0 = blockIdx.x * 32, c0 = blockIdx.y * 32;
  int tx = threadIdx.x & 31, ty = threadIdx.x >> 5;   // 32 x 8
#pragma unroll
  for (int i = 0; i < 4; i++) {
    int s = s0 + ty + i * 8;
    tile[ty + i * 8][tx] = g_kvb[((size_t)(b * SEQ + s)) * KVB + h * 256 + 128 + c0 + tx];
  }
  __syncthreads();
#pragma unroll
  for (int i = 0; i < 4; i++) {
    int c = c0 + ty + i * 8;
    float v = tile[tx][ty + i * 8];
    g_vh[((size_t)bh * VD + c) * SEQ + s0 + tx] = uif(f2tf(v));
  }
}

// ---------------- persistent tensor-core causal flash attention ----------------
// 148 persistent CTAs pull (qt, bh) units from g_ctr in descending-qt order.
// BM=128 q-rows, BN=64 kv-rows, 512 threads = 16 warps (8 wm x 2 wn).
#define QST 196
#define KST 196
#define VTS 68
#define PST 68
__global__ __launch_bounds__(512) void attn_kernel(float scale)
{
  extern __shared__ float sm[];
  float* Qs    = sm;                  // 128*196
  float* Kh    = Qs + BM * QST;       // 64*196
  float* Vh    = Kh + 64 * KST;       // 128*68
  float* Ps    = Vh + 128 * VTS;      // 128*68
  float* pmax  = Ps + BM * PST;       // 256
  float* psum  = pmax + 256;          // 256
  float* row_m = psum + 256;          // 128
  float* row_l = row_m + 128;         // 128
  float* row_c = row_l + 128;         // 128
  __shared__ int s_unit;

  const int tid = threadIdx.x;
  const int lane = tid & 31, warp = tid >> 5;
  const int g = lane >> 2, t = lane & 3;
  const int wm = warp >> 1, wn = warp & 1;
  const int r0 = wm * 16 + g, r1 = r0 + 8;

  for (;;) {
    __syncthreads();            // smem reuse guard (prev unit fully done)
    if (tid == 0) s_unit = atomicAdd(&g_ctr, 1);
    __syncthreads();
    const int u = s_unit;
    if (u >= NUNITS) break;
    const int qt = (NQT2 - 1) - (u >> 5);   // descending size
    const int bhid = u & 31;
    const int b = bhid >> 4, h = bhid & 15;
    const int rowbase = b * SEQ;
    const int q0 = qt * BM;
    const int nkt = 2 * qt + 2;

    const float* khg = g_kh + (size_t)bhid * SEQ * QKD;
    const float* vhg = g_vh + (size_t)bhid * VD * SEQ;

    auto issueK = [&](int k0) {
#pragma unroll
      for (int it = 0; it < 6; it++) {
        int ch = tid + it * 512;                    // 3072 chunks
        int r = ch / 48, cc = ch - r * 48;
        cpa16(&Kh[r * KST + cc * 4], khg + (size_t)(k0 + r) * QKD + cc * 4, true);
      }
      CP_COMMIT;
    };
    auto issueV = [&](int k0) {
#pragma unroll
      for (int it = 0; it < 4; it++) {
        int ch = tid + it * 512;                    // 2048 chunks
        int c = ch >> 4, cc = ch & 15;
        cpa16(&Vh[c * VTS + cc * 4], vhg + (size_t)c * SEQ + k0 + cc * 4, true);
      }
      CP_COMMIT;
    };

    if (tid < 128) { row_m[tid] = -1e30f; row_l[tid] = 0.f; }

    issueK(0);
    issueV(0);

    // Q tile (scaled fp32; reference's q-rotary is dead code -> raw projection)
    for (int idx = tid; idx < BM * QKD / 4; idx += 512) {
      int r = idx / 48, c4 = (idx - r * 48) * 4;
      float4 v = *(const float4*)&g_q[(size_t)(rowbase + q0 + r) * QOUT + h * QKD + c4];
      *(float4*)&Qs[r * QST + c4] =
          make_float4(v.x * scale, v.y * scale, v.z * scale, v.w * scale);
    }

    float oacc[8][4];
#pragma unroll
    for (int j = 0; j < 8; j++)
#pragma unroll
      for (int r = 0; r < 4; r++) oacc[j][r] = 0.f;

    for (int kt = 0; kt < nkt; kt++) {
      const int k0 = kt * 64;
      CP_WAIT1;                 // Kh(kt) done (V(kt) may pend)
      __syncthreads();

      // ---- scores: 2-term (Qhi+Qlo) x Khi ----
      float sacc[4][4];
#pragma unroll
      for (int j = 0; j < 4; j++)
#pragma unroll
        for (int r = 0; r < 4; r++) sacc[j][r] = 0.f;

#pragma unroll 4
      for (int kk = 0; kk < QKD / 8; kk++) {
        const int ko = kk * 8;
        uint32_t ah[4], al[4];
        tfsplit(Qs[r0 * QST + ko + t],     ah[0], al[0]);
        tfsplit(Qs[r1 * QST + ko + t],     ah[1], al[1]);
        tfsplit(Qs[r0 * QST + ko + t + 4], ah[2], al[2]);
        tfsplit(Qs[r1 * QST + ko + t + 4], ah[3], al[3]);
#pragma unroll
        for (int jb = 0; jb < 4; jb++) {
          int nr = wn * 32 + jb * 8 + g;
          uint32_t bh2[2] = { __float_as_uint(Kh[nr * KST + ko + t]),
                              __float_as_uint(Kh[nr * KST + ko + t + 4]) };
          mma_tf32(sacc[jb], ah, bh2);
          mma_tf32(sacc[jb], al, bh2);
        }
      }

      if (kt >= 2 * qt) {       // diagonal-straddling tiles
#pragma unroll
        for (int jb = 0; jb < 4; jb++) {
          int cb = k0 + wn * 32 + jb * 8 + 2 * t;   // global col
          if (cb     > q0 + r0) sacc[jb][0] = -1e30f;
          if (cb + 1 > q0 + r0) sacc[jb][1] = -1e30f;
          if (cb     > q0 + r1) sacc[jb][2] = -1e30f;
          if (cb + 1 > q0 + r1) sacc[jb][3] = -1e30f;
        }
      }

      // ---- online softmax ----
      float mo0 = row_m[r0], mo1 = row_m[r1];
      float px0 = -1e30f, px1 = -1e30f;
#pragma unroll
      for (int jb = 0; jb < 4; jb++) {
        px0 = fmaxf(px0, fmaxf(sacc[jb][0], sacc[jb][1]));
        px1 = fmaxf(px1, fmaxf(sacc[jb][2], sacc[jb][3]));
      }
      px0 = fmaxf(px0, __shfl_xor_sync(0xffffffffu, px0, 1));
      px0 = fmaxf(px0, __shfl_xor_sync(0xffffffffu, px0, 2));
      px1 = fmaxf(px1, __shfl_xor_sync(0xffffffffu, px1, 1));
      px1 = fmaxf(px1, __shfl_xor_sync(0xffffffffu, px1, 2));
      if (t == 0) { pmax[r0 * 2 + wn] = px0; pmax[r1 * 2 + wn] = px1; }
      __syncthreads();           // all warps done reading Kh

      float mn0 = fmaxf(mo0, fmaxf(pmax[r0 * 2], pmax[r0 * 2 + 1]));
      float mn1 = fmaxf(mo1, fmaxf(pmax[r1 * 2], pmax[r1 * 2 + 1]));
      float s0 = 0.f, s1 = 0.f;
#pragma unroll
      for (int jb = 0; jb < 4; jb++) {
        float p0 = __expf(sacc[jb][0] - mn0);
        float p1 = __expf(sacc[jb][1] - mn0);
        float p2 = __expf(sacc[jb][2] - mn1);
        float p3 = __expf(sacc[jb][3] - mn1);
        int cb = wn * 32 + jb * 8 + 2 * t;
        *(float2*)&Ps[r0 * PST + cb] = make_float2(p0, p1);
        *(float2*)&Ps[r1 * PST + cb] = make_float2(p2, p3);
        s0 += p0 + p1; s1 += p2 + p3;
      }
      s0 += __shfl_xor_sync(0xffffffffu, s0, 1);
      s0 += __shfl_xor_sync(0xffffffffu, s0, 2);
      s1 += __shfl_xor_sync(0xffffffffu, s1, 1);
      s1 += __shfl_xor_sync(0xffffffffu, s1, 2);
      if (t == 0) {
        psum[r0 * 2 + wn] = s0; psum[r1 * 2 + wn] = s1;
        if (wn == 0) {
          row_c[r0] = __expf(mo0 - mn0); row_m[r0] = mn0;
          row_c[r1] = __expf(mo1 - mn1); row_m[r1] = mn1;
        }
      }
      __syncthreads();

      // Kh free -> prefetch next K; then wait V(kt)
      if (kt < nkt - 1) { issueK((kt + 1) * 64); CP_WAIT1; }
      else CP_WAIT0;
      __syncthreads();

      if (wn == 0 && t == 0) {
        row_l[r0] = row_l[r0] * row_c[r0] + psum[r0 * 2] + psum[r0 * 2 + 1];
        row_l[r1] = row_l[r1] * row_c[r1] + psum[r1 * 2] + psum[r1 * 2 + 1];
      }

      // ---- PV: P x Vhi ----
      {
        float c0 = row_c[r0], c1 = row_c[r1];
#pragma unroll
        for (int jb = 0; jb < 8; jb++) {
          oacc[jb][0] *= c0; oacc[jb][1] *= c0;
          oacc[jb][2] *= c1; oacc[jb][3] *= c1;
        }
      }
#pragma unroll 2
      for (int kk = 0; kk < 8; kk++) {
        const int ko = kk * 8;
        uint32_t ah[4];
        ah[0] = f2tf(Ps[r0 * PST + ko + t]);
        ah[1] = f2tf(Ps[r1 * PST + ko + t]);
        ah[2] = f2tf(Ps[r0 * PST + ko + t + 4]);
        ah[3] = f2tf(Ps[r1 * PST + ko + t + 4]);
#pragma unroll
        for (int jb = 0; jb < 8; jb++) {
          int nr = wn * 64 + jb * 8 + g;
          uint32_t bh2[2] = { __float_as_uint(Vh[nr * VTS + ko + t]),
                              __float_as_uint(Vh[nr * VTS + ko + t + 4]) };
          mma_tf32(oacc[jb], ah, bh2);
        }
      }
      __syncthreads();           // all warps done reading Vh/Ps

      if (kt < nkt - 1) issueV((kt + 1) * 64);
    }

    // epilogue: tf32-round + k-permute columns (g_attn is the wo GEMM's A operand)
    float inv0 = 1.f / row_l[r0], inv1 = 1.f / row_l[r1];
#pragma unroll
    for (int jb = 0; jb < 8; jb++) {
      int base8 = h * VD + wn * 64 + jb * 8;          // multiple of 8
      int p0 = base8 + kperm(2 * t);
      int p1 = base8 + kperm(2 * t + 1);
      g_attn[(size_t)(rowbase + q0 + r0) * (NH * VD) + p0] = uif(f2tf(oacc[jb][0] * inv0));
      g_attn[(size_t)(rowbase + q0 + r0) * (NH * VD) + p1] = uif(f2tf(oacc[jb][1] * inv0));
      g_attn[(size_t)(rowbase + q0 + r1) * (NH * VD) + p0] = uif(f2tf(oacc[jb][2] * inv1));
      g_attn[(size_t)(rowbase + q0 + r1) * (NH * VD) + p1] = uif(f2tf(oacc[jb][3] * inv1));
    }
  }
}

// ---------------- launcher ----------------
extern "C" void kernel_launch(void* const* d_in, const int* in_sizes, int n_in,
                              void* d_out, int out_size)
{
  const float *x = nullptr, *wq = nullptr, *wkv_a = nullptr, *kvnw = nullptr,
              *wkv_b = nullptr, *wo = nullptr, *fcos = nullptr, *fsin = nullptr;
  for (int i = 0; i < n_in; i++) {
    const float* p = (const float*)d_in[i];
    switch (in_sizes[i]) {
      case 8388608: x = p; break;
      case 6291456: wq = p; break;
      case 1179648: wkv_a = p; break;
      case 512:     kvnw = p; break;
      case 2097152: wkv_b = p; break;
      case 4194304: wo = p; break;
      case 65536:   if (!fcos) fcos = p; else fsin = p; break;
      default: break;
    }
  }
  float* out = (float*)d_out;

  float *p_q, *p_kvc, *p_attn, *p_xr, *p_wqr, *p_wkvar, *p_wkvbr, *p_wor, *p_kv, *p_kvb;
  cudaGetSymbolAddress((void**)&p_q,     g_q);
  cudaGetSymbolAddress((void**)&p_kv,    g_kv);
  cudaGetSymbolAddress((void**)&p_kvc,   g_kvc);
  cudaGetSymbolAddress((void**)&p_kvb,   g_kvb);
  cudaGetSymbolAddress((void**)&p_attn,  g_attn);
  cudaGetSymbolAddress((void**)&p_xr,    g_xr);
  cudaGetSymbolAddress((void**)&p_wqr,   g_wqr);
  cudaGetSymbolAddress((void**)&p_wkvar, g_wkvar);
  cudaGetSymbolAddress((void**)&p_wkvbr, g_wkvbr);
  cudaGetSymbolAddress((void**)&p_wor,   g_wor);

  double mm = 0.1 * log(40.0) + 1.0;
  float scale = (float)((1.0 / sqrt(192.0)) * mm * mm);

  auto rnd = [&](const float* s, float* d, int n) {
    round_perm<<<(n / 8 + 255) / 256, 256>>>(s, d, n);
  };
  rnd(x,     p_xr,    ROWS * DIM);
  rnd(wq,    p_wqr,   QOUT * DIM);
  rnd(wkv_a, p_wkvar, KVA * DIM);
  rnd(wkv_b, p_wkvbr, KVB * KV_LORA);
  rnd(wo,    p_wor,   DIM * NH * VD);

  const size_t gsmem = (size_t)(4 * 128 * GST) * sizeof(float);   // 81920 B
  cudaFuncSetAttribute(tgemm_nt, cudaFuncAttributeMaxDynamicSharedMemorySize, (int)gsmem);

  tgemm_nt<<<dim3(QOUT / 128, ROWS / 128), 256, gsmem>>>(p_xr, p_wqr, p_q, ROWS, QOUT, DIM);
  tgemm_nt<<<dim3((KVA + 127) / 128, ROWS / 128), 256, gsmem>>>(p_xr, p_wkvar, p_kv, ROWS, KVA, DIM);
  kv_post_kernel<<<ROWS, 128>>>(kvnw, fcos, fsin);
  tgemm_nt<<<dim3(KVB / 128, ROWS / 128), 256, gsmem>>>(p_kvc, p_wkvbr, p_kvb, ROWS, KVB, KV_LORA);
  {
    size_t nkh = (size_t)Bsz * NH * SEQ * QKD;
    prep_kh_kernel<<<(unsigned)((nkh + 255) / 256), 256>>>();
    prep_v_kernel<<<dim3(SEQ / 32, VD / 32, Bsz * NH), 256>>>();
    reset_ctr_kernel<<<1, 1>>>();
  }
  {
    size_t smem = (size_t)(BM * QST + 64 * KST + 128 * VTS + BM * PST + 256 + 256 + 384)
                  * sizeof(float);   // ~224 KB
    cudaFuncSetAttribute(attn_kernel, cudaFuncAttributeMaxDynamicSharedMemorySize, (int)smem);
    attn_kernel<<<148, 512, smem>>>(scale);
  }
  tgemm_nt<<<dim3(DIM / 128, ROWS / 128), 256, gsmem>>>(p_attn, p_wor, out, ROWS, DIM, NH * VD);
}